// round 10
// baseline (speedup 1.0000x reference)
#include <cuda_runtime.h>
#include <cuda_bf16.h>
#include <stdint.h>
#include <math.h>

// ---------------------------------------------------------------------------
// Problem constants
// ---------------------------------------------------------------------------
#define BATCH 4
#define SEQ   2048
#define DIM   1024
#define NROWS (BATCH * SEQ)          // 8192

// ---------------------------------------------------------------------------
// Scratch (device globals: allocation-free)
// ---------------------------------------------------------------------------
__device__ __align__(128) __nv_bfloat16 g_xhi[(size_t)NROWS * DIM];
__device__ __align__(128) __nv_bfloat16 g_xlo[(size_t)NROWS * DIM];
__device__ __align__(128) __nv_bfloat16 g_whi[(size_t)3 * DIM * DIM];
__device__ __align__(128) __nv_bfloat16 g_wlo[(size_t)3 * DIM * DIM];
__device__ __align__(128) __nv_bfloat16 g_qhi[(size_t)NROWS * DIM];
__device__ __align__(128) __nv_bfloat16 g_qlo[(size_t)NROWS * DIM];
__device__ __align__(128) __nv_bfloat16 g_khi[(size_t)NROWS * DIM];
__device__ __align__(128) __nv_bfloat16 g_klo[(size_t)NROWS * DIM];
__device__ __align__(128) __nv_bfloat16 g_vthi[(size_t)DIM * NROWS];   // [D, B*S]
__device__ __align__(128) __nv_bfloat16 g_vtlo[(size_t)DIM * NROWS];
__device__ __align__(128) float         g_s[(size_t)BATCH * SEQ * SEQ];
__device__ __align__(128) __nv_bfloat16 g_ahi[(size_t)BATCH * SEQ * SEQ];
__device__ __align__(128) __nv_bfloat16 g_alo[(size_t)BATCH * SEQ * SEQ];

// ---------------------------------------------------------------------------
// PTX helpers (baseline PTX only — NO tcgen05: harness ptxas targets sm_103)
// ---------------------------------------------------------------------------
__device__ __forceinline__ uint32_t smem_u32(const void* p) {
    uint32_t a;
    asm("{ .reg .u64 t; cvta.to.shared.u64 t, %1; cvt.u32.u64 %0, t; }"
        : "=r"(a) : "l"(p));
    return a;
}

__device__ __forceinline__ void ldmatrix_x4(uint32_t& r0, uint32_t& r1,
                                            uint32_t& r2, uint32_t& r3,
                                            uint32_t addr) {
    asm volatile("ldmatrix.sync.aligned.m8n8.x4.shared.b16 {%0,%1,%2,%3}, [%4];"
                 : "=r"(r0), "=r"(r1), "=r"(r2), "=r"(r3) : "r"(addr));
}

__device__ __forceinline__ void mma_bf16(float* d, const uint32_t* a,
                                         const uint32_t* b) {
    asm volatile(
        "mma.sync.aligned.m16n8k16.row.col.f32.bf16.bf16.f32 "
        "{%0,%1,%2,%3}, {%4,%5,%6,%7}, {%8,%9}, {%0,%1,%2,%3};"
        : "+f"(d[0]), "+f"(d[1]), "+f"(d[2]), "+f"(d[3])
        : "r"(a[0]), "r"(a[1]), "r"(a[2]), "r"(a[3]),
          "r"(b[0]), "r"(b[1]));
}

#define CP_ASYNC16(smem, gptr) \
    asm volatile("cp.async.cg.shared.global [%0], [%1], 16;" \
                 :: "r"(smem), "l"(gptr) : "memory")
#define CP_COMMIT() asm volatile("cp.async.commit_group;" ::: "memory")
#define CP_WAIT(n)  asm volatile("cp.async.wait_group %0;" :: "n"(n) : "memory")

__device__ __forceinline__ void split2_store(__nv_bfloat16* hi, __nv_bfloat16* lo,
                                             long idx, float v0, float v1)
{
    __nv_bfloat16 h0 = __float2bfloat16(v0);
    __nv_bfloat16 h1 = __float2bfloat16(v1);
    *(__nv_bfloat162*)(hi + idx) = __halves2bfloat162(h0, h1);
    *(__nv_bfloat162*)(lo + idx) = __halves2bfloat162(
        __float2bfloat16(v0 - __bfloat162float(h0)),
        __float2bfloat16(v1 - __bfloat162float(h1)));
}

// ---------------------------------------------------------------------------
// bf16x3 GEMM via mma.sync + cp.async 4-stage pipeline.
//   C[m,n] = alpha * sum_k A[m,k]*B[n,k] (+ bias)
//   A ~ Ahi+Alo rm [M,K] lda; B ~ Bhi+Blo rm [N,K] ldb; K logically tripled
//   via 3 segments (hi,hi),(hi,lo),(lo,hi) into one fp32 accumulator.
//   Tile 128x128, BK=32, 256 thr = 8 warps (2m x 4n), warp tile 64x32.
//   smem rows padded to 40 elems (80B = 5*16B): aligned + conflict-free.
// EPI: 0 = fp32 out (alpha, no bias)
//      1 = bf16 hi/lo split out, column bias
//      2 = bf16 hi/lo split out, row bias
// ---------------------------------------------------------------------------
#define PAD    40
#define SMB    (128 * PAD * 2)   // bytes per stage per matrix (10240)
#define NSTAGE 4
#define SMEM_TOTAL (2 * NSTAGE * SMB)   // 81920

template <int EPI>
__global__ void __launch_bounds__(256, 2)
gemm_bf16x3(const __nv_bfloat16* __restrict__ Ahi, const __nv_bfloat16* __restrict__ Alo,
            const __nv_bfloat16* __restrict__ Bhi, const __nv_bfloat16* __restrict__ Blo,
            const float* __restrict__ bias,
            float* __restrict__ Cf,
            __nv_bfloat16* __restrict__ Chi, __nv_bfloat16* __restrict__ Clo,
            int K, int lda, int ldb, int ldc,
            long sA, long sB, long sC, float alpha)
{
    extern __shared__ __align__(128) char dsm[];
    const uint32_t sa_base = smem_u32(dsm);
    const uint32_t sb_base = sa_base + NSTAGE * SMB;

    const int tid  = threadIdx.x;
    const int lane = tid & 31;
    const int wid  = tid >> 5;
    const int wm   = (wid >> 2) * 64;   // warp m origin (0 or 64)
    const int wn   = (wid & 3) * 32;    // warp n origin (0,32,64,96)

    const long m0 = (long)blockIdx.x * 128;
    const long n0 = (long)blockIdx.y * 128;
    const int  z  = blockIdx.z;
    const int  KT = K >> 5;             // 32-wide K tiles per segment
    const int  NT = 3 * KT;

    const __nv_bfloat16* Ah = Ahi + (long)z * sA;
    const __nv_bfloat16* Al = Alo + (long)z * sA;
    const __nv_bfloat16* Bh = Bhi + (long)z * sB;
    const __nv_bfloat16* Bl = Blo + (long)z * sB;

    float acc[4][4][4];
    #pragma unroll
    for (int i = 0; i < 4; i++)
        #pragma unroll
        for (int j = 0; j < 4; j++)
            #pragma unroll
            for (int r = 0; r < 4; r++) acc[i][j][r] = 0.0f;

    // per-thread load slots: 2 x (row, k-chunk) covering 128x32 per matrix
    const int r0_ = tid >> 2;           // 0..63
    const int j0_ = tid & 3;
    // second slot: id = tid + 256 -> row = 64 + r0_, same j

    auto issue_tile = [&](int t, int buf) {
        const int seg = t / KT;
        const long kk = (long)(t - seg * KT) << 5;
        const __nv_bfloat16* Ap = (seg < 2)  ? Ah : Al;
        const __nv_bfloat16* Bp = (seg != 1) ? Bh : Bl;
        const uint32_t sa = sa_base + buf * SMB;
        const uint32_t sb = sb_base + buf * SMB;
        #pragma unroll
        for (int i = 0; i < 2; i++) {
            const int row = r0_ + i * 64;
            const uint32_t so = (uint32_t)(row * PAD + j0_ * 8) * 2;
            CP_ASYNC16(sa + so, Ap + (m0 + row) * (long)lda + kk + j0_ * 8);
            CP_ASYNC16(sb + so, Bp + (n0 + row) * (long)ldb + kk + j0_ * 8);
        }
        CP_COMMIT();
    };

    auto compute = [&](int buf) {
        const uint32_t ab = sa_base + buf * SMB;
        const uint32_t bb = sb_base + buf * SMB;
        #pragma unroll
        for (int ks = 0; ks < 2; ks++) {
            uint32_t af[4][4], bf[4][2];
            #pragma unroll
            for (int mt = 0; mt < 4; mt++) {
                const int row  = wm + mt * 16 + (lane & 15);
                const int koff = ks * 16 + ((lane >> 4) << 3);
                ldmatrix_x4(af[mt][0], af[mt][1], af[mt][2], af[mt][3],
                            ab + (row * PAD + koff) * 2);
            }
            #pragma unroll
            for (int h = 0; h < 2; h++) {
                const int row  = wn + h * 16 + (lane & 7) + ((lane >> 4) << 3);
                const int koff = ks * 16 + ((lane >> 3) & 1) * 8;
                ldmatrix_x4(bf[h * 2][0], bf[h * 2][1],
                            bf[h * 2 + 1][0], bf[h * 2 + 1][1],
                            bb + (row * PAD + koff) * 2);
            }
            #pragma unroll
            for (int mt = 0; mt < 4; mt++)
                #pragma unroll
                for (int nt = 0; nt < 4; nt++)
                    mma_bf16(acc[mt][nt], af[mt], bf[nt]);
        }
    };

    // 4-stage pipeline, one barrier per iteration.
    // issue at iter t overwrites buf (t-1)&3, whose readers (compute(t-1))
    // all passed this iteration's __syncthreads.
    #pragma unroll
    for (int s = 0; s < NSTAGE - 1; s++) issue_tile(s, s);
    for (int t = 0; t < NT; t++) {
        CP_WAIT(NSTAGE - 2);
        __syncthreads();
        if (t + NSTAGE - 1 < NT) issue_tile(t + NSTAGE - 1, (t + NSTAGE - 1) & 3);
        compute(t & 3);
    }

    // epilogue
    const int g   = lane >> 2;
    const int tg2 = (lane & 3) * 2;
    #pragma unroll
    for (int mt = 0; mt < 4; mt++) {
        #pragma unroll
        for (int half = 0; half < 2; half++) {
            const long row = m0 + wm + mt * 16 + g + half * 8;
            const long rbase = (long)z * sC + row * (long)ldc;
            #pragma unroll
            for (int nt = 0; nt < 4; nt++) {
                const long col = n0 + wn + nt * 8 + tg2;
                float v0 = acc[mt][nt][half * 2 + 0] * alpha;
                float v1 = acc[mt][nt][half * 2 + 1] * alpha;
                if (EPI == 0) {
                    *(float2*)(Cf + rbase + col) = make_float2(v0, v1);
                } else if (EPI == 1) {
                    v0 += bias[col];
                    v1 += bias[col + 1];
                    split2_store(Chi, Clo, rbase + col, v0, v1);
                } else {
                    const float b = bias[row];
                    split2_store(Chi, Clo, rbase + col, v0 + b, v1 + b);
                }
            }
        }
    }
}

// ---------------------------------------------------------------------------
// fp32 -> bf16 hi/lo split (x and W pre-passes)
// ---------------------------------------------------------------------------
__device__ __forceinline__ void split_store4(__nv_bfloat16* hi, __nv_bfloat16* lo,
                                             long idx, float4 v)
{
    split2_store(hi, lo, idx,     v.x, v.y);
    split2_store(hi, lo, idx + 2, v.z, v.w);
}

__global__ void __launch_bounds__(256)
split_kernel(const float* __restrict__ in, __nv_bfloat16* __restrict__ hi,
             __nv_bfloat16* __restrict__ lo, long n)
{
    long i = ((long)blockIdx.x * 256 + threadIdx.x) * 4;
    if (i >= n) return;
    float4 f = *(const float4*)(in + i);
    split_store4(hi, lo, i, f);
}

// ---------------------------------------------------------------------------
// Row softmax fused with hi/lo split of attn probabilities.
// ---------------------------------------------------------------------------
__global__ void __launch_bounds__(256)
softmax_split_kernel(const float* __restrict__ S,
                     __nv_bfloat16* __restrict__ Ahi,
                     __nv_bfloat16* __restrict__ Alo)
{
    __shared__ float red[8];
    __shared__ float bcast;

    const long row = blockIdx.x;
    const float4* p4 = (const float4*)(S + row * (long)SEQ);
    const int tid  = threadIdx.x;
    const int lane = tid & 31;
    const int wid  = tid >> 5;

    float4 v0 = p4[tid];
    float4 v1 = p4[tid + 256];

    float m = fmaxf(fmaxf(fmaxf(v0.x, v0.y), fmaxf(v0.z, v0.w)),
                    fmaxf(fmaxf(v1.x, v1.y), fmaxf(v1.z, v1.w)));
    #pragma unroll
    for (int o = 16; o > 0; o >>= 1) m = fmaxf(m, __shfl_xor_sync(0xffffffffu, m, o));
    if (lane == 0) red[wid] = m;
    __syncthreads();
    if (wid == 0) {
        float x = (lane < 8) ? red[lane] : -3.4e38f;
        #pragma unroll
        for (int o = 4; o > 0; o >>= 1) x = fmaxf(x, __shfl_xor_sync(0xffffffffu, x, o));
        if (lane == 0) bcast = x;
    }
    __syncthreads();
    m = bcast;
    __syncthreads();

    v0.x = __expf(v0.x - m); v0.y = __expf(v0.y - m);
    v0.z = __expf(v0.z - m); v0.w = __expf(v0.w - m);
    v1.x = __expf(v1.x - m); v1.y = __expf(v1.y - m);
    v1.z = __expf(v1.z - m); v1.w = __expf(v1.w - m);
    float s = (v0.x + v0.y + v0.z + v0.w) + (v1.x + v1.y + v1.z + v1.w);
    #pragma unroll
    for (int o = 16; o > 0; o >>= 1) s += __shfl_xor_sync(0xffffffffu, s, o);
    if (lane == 0) red[wid] = s;
    __syncthreads();
    if (wid == 0) {
        float x = (lane < 8) ? red[lane] : 0.0f;
        #pragma unroll
        for (int o = 4; o > 0; o >>= 1) x += __shfl_xor_sync(0xffffffffu, x, o);
        if (lane == 0) bcast = x;
    }
    __syncthreads();
    const float inv = 1.0f / bcast;

    v0.x *= inv; v0.y *= inv; v0.z *= inv; v0.w *= inv;
    v1.x *= inv; v1.y *= inv; v1.z *= inv; v1.w *= inv;

    const long base = row * (long)SEQ;
    split_store4(Ahi, Alo, base + tid * 4, v0);
    split_store4(Ahi, Alo, base + 1024 + tid * 4, v1);
}

// ---------------------------------------------------------------------------
// kernel_launch
// inputs: x, Wq, bq, Wk, bk, Wv, bv
// ---------------------------------------------------------------------------
extern "C" void kernel_launch(void* const* d_in, const int* in_sizes, int n_in,
                              void* d_out, int out_size)
{
    const float* x  = (const float*)d_in[0];
    const float* Wq = (const float*)d_in[1];
    const float* bq = (const float*)d_in[2];
    const float* Wk = (const float*)d_in[3];
    const float* bk = (const float*)d_in[4];
    const float* Wv = (const float*)d_in[5];
    const float* bv = (const float*)d_in[6];
    float* out = (float*)d_out;

    __nv_bfloat16 *xhi, *xlo, *whi, *wlo, *qhi, *qlo, *khi, *klo, *vthi, *vtlo, *ahi, *alo;
    float *sc;
    cudaGetSymbolAddress((void**)&xhi,  g_xhi);
    cudaGetSymbolAddress((void**)&xlo,  g_xlo);
    cudaGetSymbolAddress((void**)&whi,  g_whi);
    cudaGetSymbolAddress((void**)&wlo,  g_wlo);
    cudaGetSymbolAddress((void**)&qhi,  g_qhi);
    cudaGetSymbolAddress((void**)&qlo,  g_qlo);
    cudaGetSymbolAddress((void**)&khi,  g_khi);
    cudaGetSymbolAddress((void**)&klo,  g_klo);
    cudaGetSymbolAddress((void**)&vthi, g_vthi);
    cudaGetSymbolAddress((void**)&vtlo, g_vtlo);
    cudaGetSymbolAddress((void**)&sc,   g_s);
    cudaGetSymbolAddress((void**)&ahi,  g_ahi);
    cudaGetSymbolAddress((void**)&alo,  g_alo);

    cudaFuncSetAttribute(gemm_bf16x3<0>, cudaFuncAttributeMaxDynamicSharedMemorySize, SMEM_TOTAL);
    cudaFuncSetAttribute(gemm_bf16x3<1>, cudaFuncAttributeMaxDynamicSharedMemorySize, SMEM_TOTAL);
    cudaFuncSetAttribute(gemm_bf16x3<2>, cudaFuncAttributeMaxDynamicSharedMemorySize, SMEM_TOTAL);

    const long nxd = (long)NROWS * DIM;
    const long nww = (long)DIM * DIM;

    // split inputs (x and weights only; q/k/v splits are fused into epilogues)
    split_kernel<<<(int)(nxd / 4 / 256), 256>>>(x,  xhi, xlo, nxd);
    split_kernel<<<(int)(nww / 4 / 256), 256>>>(Wq, whi,           wlo,           nww);
    split_kernel<<<(int)(nww / 4 / 256), 256>>>(Wk, whi + nww,     wlo + nww,     nww);
    split_kernel<<<(int)(nww / 4 / 256), 256>>>(Wv, whi + 2 * nww, wlo + 2 * nww, nww);

    // Q, K projections: [8192,1024] x W^T + colbias -> split bf16 [8192,1024]
    {
        dim3 grid(NROWS / 128, DIM / 128, 1);
        gemm_bf16x3<1><<<grid, 256, SMEM_TOTAL>>>(xhi, xlo, whi,       wlo,       bq,
                                                  nullptr, qhi, qlo,
                                                  DIM, DIM, DIM, DIM, 0, 0, 0, 1.0f);
        gemm_bf16x3<1><<<grid, 256, SMEM_TOTAL>>>(xhi, xlo, whi + nww, wlo + nww, bk,
                                                  nullptr, khi, klo,
                                                  DIM, DIM, DIM, DIM, 0, 0, 0, 1.0f);
    }
    // V projection, transposed: Vt[d, s] = sum_k Wv[d,k] x[s,k] + bv[d]
    //   A = Wv [1024,1024], B = x [8192,1024], C = Vt [1024, 8192], row bias
    {
        dim3 grid(DIM / 128, NROWS / 128, 1);
        gemm_bf16x3<2><<<grid, 256, SMEM_TOTAL>>>(whi + 2 * nww, wlo + 2 * nww, xhi, xlo, bv,
                                                  nullptr, vthi, vtlo,
                                                  DIM, DIM, DIM, NROWS, 0, 0, 0, 1.0f);
    }

    // scores: per batch [2048,1024] x [2048,1024]^T * 1/32 -> fp32
    {
        dim3 grid(SEQ / 128, SEQ / 128, BATCH);
        gemm_bf16x3<0><<<grid, 256, SMEM_TOTAL>>>(qhi, qlo, khi, klo, nullptr,
                                                  sc, nullptr, nullptr,
                                                  DIM, DIM, DIM, SEQ,
                                                  (long)SEQ * DIM, (long)SEQ * DIM,
                                                  (long)SEQ * SEQ, 1.0f / 32.0f);
    }

    // softmax + split attn
    softmax_split_kernel<<<NROWS, 256>>>(sc, ahi, alo);

    // out: per batch attn[2048,2048] x Vt[:, b*2048 : b*2048+2048]^T -> fp32
    //   B = Vt [1024 rows, ldb=8192], batch offset = 2048 columns (k offset)
    {
        dim3 grid(SEQ / 128, DIM / 128, BATCH);
        gemm_bf16x3<0><<<grid, 256, SMEM_TOTAL>>>(ahi, alo, vthi, vtlo, nullptr,
                                                  out, nullptr, nullptr,
                                                  SEQ, SEQ, NROWS, DIM,
                                                  (long)SEQ * SEQ, (long)SEQ,
                                                  (long)SEQ * DIM, 1.0f);
    }
}

// round 11
// speedup vs baseline: 1.1130x; 1.1130x over previous
#include <cuda_runtime.h>
#include <cuda_bf16.h>
#include <stdint.h>
#include <math.h>

// ---------------------------------------------------------------------------
// Problem constants
// ---------------------------------------------------------------------------
#define BATCH 4
#define SEQ   2048
#define DIM   1024
#define NROWS (BATCH * SEQ)          // 8192

// ---------------------------------------------------------------------------
// Scratch (device globals: allocation-free; zero-initialized by CUDA)
// ---------------------------------------------------------------------------
__device__ __align__(128) __nv_bfloat16 g_xhi[(size_t)NROWS * DIM];
__device__ __align__(128) __nv_bfloat16 g_xlo[(size_t)NROWS * DIM];
__device__ __align__(128) __nv_bfloat16 g_wvhi[(size_t)DIM * DIM];
__device__ __align__(128) __nv_bfloat16 g_wvlo[(size_t)DIM * DIM];
__device__ __align__(128) __nv_bfloat16 g_wqthi[(size_t)DIM * DIM];  // Wq^T split
__device__ __align__(128) __nv_bfloat16 g_wqtlo[(size_t)DIM * DIM];
__device__ __align__(128) __nv_bfloat16 g_wkthi[(size_t)DIM * DIM];  // Wk^T split
__device__ __align__(128) __nv_bfloat16 g_wktlo[(size_t)DIM * DIM];
__device__ __align__(128) __nv_bfloat16 g_mthi[(size_t)DIM * DIM];   // Mt = (Wq^T Wk)^T
__device__ __align__(128) __nv_bfloat16 g_mtlo[(size_t)DIM * DIM];
__device__ __align__(128) __nv_bfloat16 g_phi[(size_t)NROWS * DIM];  // P = x M
__device__ __align__(128) __nv_bfloat16 g_plo[(size_t)NROWS * DIM];
__device__ __align__(128) __nv_bfloat16 g_vthi[(size_t)DIM * NROWS]; // Vt [D, B*S]
__device__ __align__(128) __nv_bfloat16 g_vtlo[(size_t)DIM * NROWS];
__device__ __align__(128) float         g_s[(size_t)BATCH * SEQ * SEQ];
__device__ __align__(128) __nv_bfloat16 g_ahi[(size_t)BATCH * SEQ * SEQ];
__device__ __align__(128) __nv_bfloat16 g_alo[(size_t)BATCH * SEQ * SEQ];
__device__ __align__(128) float         g_tvec[DIM];      // t = Wk^T bq
__device__ __align__(128) float         g_cst[1];         // bq . bk
__device__ __align__(128) float         g_vrow[NROWS];    // v_j (pre-scaled 1/32)
__device__ __align__(128) float         g_zero[DIM];      // zero bias (never written)

// ---------------------------------------------------------------------------
// PTX helpers (baseline PTX only — NO tcgen05: harness ptxas targets sm_103)
// ---------------------------------------------------------------------------
__device__ __forceinline__ uint32_t smem_u32(const void* p) {
    uint32_t a;
    asm("{ .reg .u64 t; cvta.to.shared.u64 t, %1; cvt.u32.u64 %0, t; }"
        : "=r"(a) : "l"(p));
    return a;
}

__device__ __forceinline__ void ldmatrix_x4(uint32_t& r0, uint32_t& r1,
                                            uint32_t& r2, uint32_t& r3,
                                            uint32_t addr) {
    asm volatile("ldmatrix.sync.aligned.m8n8.x4.shared.b16 {%0,%1,%2,%3}, [%4];"
                 : "=r"(r0), "=r"(r1), "=r"(r2), "=r"(r3) : "r"(addr));
}

__device__ __forceinline__ void mma_bf16(float* d, const uint32_t* a,
                                         const uint32_t* b) {
    asm volatile(
        "mma.sync.aligned.m16n8k16.row.col.f32.bf16.bf16.f32 "
        "{%0,%1,%2,%3}, {%4,%5,%6,%7}, {%8,%9}, {%0,%1,%2,%3};"
        : "+f"(d[0]), "+f"(d[1]), "+f"(d[2]), "+f"(d[3])
        : "r"(a[0]), "r"(a[1]), "r"(a[2]), "r"(a[3]),
          "r"(b[0]), "r"(b[1]));
}

#define CP_ASYNC16(smem, gptr) \
    asm volatile("cp.async.cg.shared.global [%0], [%1], 16;" \
                 :: "r"(smem), "l"(gptr) : "memory")
#define CP_COMMIT() asm volatile("cp.async.commit_group;" ::: "memory")
#define CP_WAIT(n)  asm volatile("cp.async.wait_group %0;" :: "n"(n) : "memory")

__device__ __forceinline__ void split2_store(__nv_bfloat16* hi, __nv_bfloat16* lo,
                                             long idx, float v0, float v1)
{
    __nv_bfloat16 h0 = __float2bfloat16(v0);
    __nv_bfloat16 h1 = __float2bfloat16(v1);
    *(__nv_bfloat162*)(hi + idx) = __halves2bfloat162(h0, h1);
    *(__nv_bfloat162*)(lo + idx) = __halves2bfloat162(
        __float2bfloat16(v0 - __bfloat162float(h0)),
        __float2bfloat16(v1 - __bfloat162float(h1)));
}

// ---------------------------------------------------------------------------
// bf16x3 GEMM via mma.sync + cp.async 3-stage pipeline, BK=64.
//   C[m,n] = alpha * sum_k A[m,k]*B[n,k] (+ bias)
//   A ~ Ahi+Alo rm [M,K] lda; B ~ Bhi+Blo rm [N,K] ldb; K logically tripled
//   via segments (hi,hi),(hi,lo),(lo,hi) into one fp32 accumulator.
//   Tile 128x128, BK=64, 256 thr = 8 warps (2m x 4n), warp tile 64x32.
//   smem rows padded to 72 elems (144B = 9*16B): aligned + conflict-free
//   (row starts at 16*i mod 128 across 8-row ldmatrix groups -> distinct).
// EPI: 0 = fp32 out (alpha, no bias)
//      1 = bf16 hi/lo split out, column bias
//      2 = bf16 hi/lo split out, row bias
// ---------------------------------------------------------------------------
#define PAD    72
#define SMB    (128 * PAD * 2)          // 18432 bytes per stage per matrix
#define NSTAGE 3
#define SMEM_TOTAL (2 * NSTAGE * SMB)   // 110592

template <int EPI>
__global__ void __launch_bounds__(256, 2)
gemm_bf16x3(const __nv_bfloat16* __restrict__ Ahi, const __nv_bfloat16* __restrict__ Alo,
            const __nv_bfloat16* __restrict__ Bhi, const __nv_bfloat16* __restrict__ Blo,
            const float* __restrict__ bias,
            float* __restrict__ Cf,
            __nv_bfloat16* __restrict__ Chi, __nv_bfloat16* __restrict__ Clo,
            int K, int lda, int ldb, int ldc,
            long sA, long sB, long sC, float alpha)
{
    extern __shared__ __align__(128) char dsm[];
    const uint32_t sa_base = smem_u32(dsm);
    const uint32_t sb_base = sa_base + NSTAGE * SMB;

    const int tid  = threadIdx.x;
    const int lane = tid & 31;
    const int wid  = tid >> 5;
    const int wm   = (wid >> 2) * 64;   // warp m origin (0 or 64)
    const int wn   = (wid & 3) * 32;    // warp n origin (0,32,64,96)

    const long m0 = (long)blockIdx.x * 128;
    const long n0 = (long)blockIdx.y * 128;
    const int  z  = blockIdx.z;
    const int  KT = K >> 6;             // 64-wide K tiles per segment
    const int  NT = 3 * KT;

    const __nv_bfloat16* Ah = Ahi + (long)z * sA;
    const __nv_bfloat16* Al = Alo + (long)z * sA;
    const __nv_bfloat16* Bh = Bhi + (long)z * sB;
    const __nv_bfloat16* Bl = Blo + (long)z * sB;

    float acc[4][4][4];
    #pragma unroll
    for (int i = 0; i < 4; i++)
        #pragma unroll
        for (int j = 0; j < 4; j++)
            #pragma unroll
            for (int r = 0; r < 4; r++) acc[i][j][r] = 0.0f;

    auto issue_tile = [&](int t, int buf) {
        const int seg = t / KT;
        const long kk = (long)(t - seg * KT) << 6;
        const __nv_bfloat16* Ap = (seg < 2)  ? Ah : Al;
        const __nv_bfloat16* Bp = (seg != 1) ? Bh : Bl;
        const uint32_t sa = sa_base + buf * SMB;
        const uint32_t sb = sb_base + buf * SMB;
        #pragma unroll
        for (int i = 0; i < 4; i++) {
            const int c   = tid + i * 256;     // 0..1023
            const int row = c >> 3;            // 0..127
            const int j   = c & 7;             // 16B chunk within 64 k
            const uint32_t so = (uint32_t)(row * PAD + j * 8) * 2;
            CP_ASYNC16(sa + so, Ap + (m0 + row) * (long)lda + kk + j * 8);
            CP_ASYNC16(sb + so, Bp + (n0 + row) * (long)ldb + kk + j * 8);
        }
        CP_COMMIT();
    };

    auto compute = [&](int buf) {
        const uint32_t ab = sa_base + buf * SMB;
        const uint32_t bb = sb_base + buf * SMB;
        #pragma unroll
        for (int ks = 0; ks < 4; ks++) {
            uint32_t af[4][4], bf[4][2];
            #pragma unroll
            for (int mt = 0; mt < 4; mt++) {
                const int row  = wm + mt * 16 + (lane & 15);
                const int koff = ks * 16 + ((lane >> 4) << 3);
                ldmatrix_x4(af[mt][0], af[mt][1], af[mt][2], af[mt][3],
                            ab + (row * PAD + koff) * 2);
            }
            #pragma unroll
            for (int h = 0; h < 2; h++) {
                const int row  = wn + h * 16 + (lane & 7) + ((lane >> 4) << 3);
                const int koff = ks * 16 + ((lane >> 3) & 1) * 8;
                ldmatrix_x4(bf[h * 2][0], bf[h * 2][1],
                            bf[h * 2 + 1][0], bf[h * 2 + 1][1],
                            bb + (row * PAD + koff) * 2);
            }
            #pragma unroll
            for (int mt = 0; mt < 4; mt++)
                #pragma unroll
                for (int nt = 0; nt < 4; nt++)
                    mma_bf16(acc[mt][nt], af[mt], bf[nt]);
        }
    };

    // 3-stage pipeline, one barrier per BK=64 iteration.
    issue_tile(0, 0);
    issue_tile(1, 1);
    for (int t = 0; t < NT; t++) {
        CP_WAIT(1);                 // group t complete
        __syncthreads();
        if (t + 2 < NT) issue_tile(t + 2, (t + 2) % 3);   // overwrites buf read at t-1
        compute(t % 3);
    }

    // epilogue
    const int g   = lane >> 2;
    const int tg2 = (lane & 3) * 2;
    #pragma unroll
    for (int mt = 0; mt < 4; mt++) {
        #pragma unroll
        for (int half = 0; half < 2; half++) {
            const long row = m0 + wm + mt * 16 + g + half * 8;
            const long rbase = (long)z * sC + row * (long)ldc;
            #pragma unroll
            for (int nt = 0; nt < 4; nt++) {
                const long col = n0 + wn + nt * 8 + tg2;
                float v0 = acc[mt][nt][half * 2 + 0] * alpha;
                float v1 = acc[mt][nt][half * 2 + 1] * alpha;
                if (EPI == 0) {
                    *(float2*)(Cf + rbase + col) = make_float2(v0, v1);
                } else if (EPI == 1) {
                    v0 += bias[col];
                    v1 += bias[col + 1];
                    split2_store(Chi, Clo, rbase + col, v0, v1);
                } else {
                    const float b = bias[row];
                    split2_store(Chi, Clo, rbase + col, v0 + b, v1 + b);
                }
            }
        }
    }
}

// ---------------------------------------------------------------------------
// fp32 -> bf16 hi/lo split
// ---------------------------------------------------------------------------
__device__ __forceinline__ void split_store4(__nv_bfloat16* hi, __nv_bfloat16* lo,
                                             long idx, float4 v)
{
    split2_store(hi, lo, idx,     v.x, v.y);
    split2_store(hi, lo, idx + 2, v.z, v.w);
}

__global__ void __launch_bounds__(256)
split_kernel(const float* __restrict__ in, __nv_bfloat16* __restrict__ hi,
             __nv_bfloat16* __restrict__ lo, long n)
{
    long i = ((long)blockIdx.x * 256 + threadIdx.x) * 4;
    if (i >= n) return;
    float4 f = *(const float4*)(in + i);
    split_store4(hi, lo, i, f);
}

// Generic transpose + split: in [R, C] fp32 -> out [C, R] bf16 hi/lo
__global__ void __launch_bounds__(256)
transpose_split_kernel(const float* __restrict__ in,
                       __nv_bfloat16* __restrict__ oh,
                       __nv_bfloat16* __restrict__ ol, int R, int C)
{
    __shared__ float t[32][33];
    const int r0 = blockIdx.y * 32;
    const int c0 = blockIdx.x * 32;
    const int tx = threadIdx.x, ty = threadIdx.y;

    #pragma unroll
    for (int j = 0; j < 4; j++)
        t[ty + 8 * j][tx] = in[(long)(r0 + ty + 8 * j) * C + c0 + tx];
    __syncthreads();
    #pragma unroll
    for (int j = 0; j < 4; j++) {
        float val = t[tx][ty + 8 * j];
        long o = (long)(c0 + ty + 8 * j) * R + r0 + tx;
        __nv_bfloat16 h = __float2bfloat16(val);
        oh[o] = h;
        ol[o] = __float2bfloat16(val - __bfloat162float(h));
    }
}

// ---------------------------------------------------------------------------
// t = Wk^T bq (t_d = sum_e bq[e] * Wk[e,d]); also c = bq . bk (block 0)
// ---------------------------------------------------------------------------
__global__ void __launch_bounds__(256)
t_kernel(const float* __restrict__ Wk, const float* __restrict__ bq,
         const float* __restrict__ bk, float* __restrict__ t,
         float* __restrict__ cst)
{
    const int d = blockIdx.x * 256 + threadIdx.x;
    float a0 = 0.f, a1 = 0.f, a2 = 0.f, a3 = 0.f;
    for (int e = 0; e < DIM; e += 4) {
        a0 += bq[e]     * Wk[(long)e * DIM + d];
        a1 += bq[e + 1] * Wk[(long)(e + 1) * DIM + d];
        a2 += bq[e + 2] * Wk[(long)(e + 2) * DIM + d];
        a3 += bq[e + 3] * Wk[(long)(e + 3) * DIM + d];
    }
    t[d] = (a0 + a1) + (a2 + a3);

    if (blockIdx.x == 0) {
        float c = 0.f;
        for (int e = threadIdx.x; e < DIM; e += 256) c += bq[e] * bk[e];
        __shared__ float red[8];
        const int lane = threadIdx.x & 31, wid = threadIdx.x >> 5;
        #pragma unroll
        for (int o = 16; o > 0; o >>= 1) c += __shfl_xor_sync(0xffffffffu, c, o);
        if (lane == 0) red[wid] = c;
        __syncthreads();
        if (threadIdx.x == 0) {
            float s = 0.f;
            #pragma unroll
            for (int w = 0; w < 8; w++) s += red[w];
            cst[0] = s;
        }
    }
}

// ---------------------------------------------------------------------------
// v_j = (x_j . t + c) / 32      (one warp per row)
// ---------------------------------------------------------------------------
__global__ void __launch_bounds__(256)
v_kernel(const float* __restrict__ x, const float* __restrict__ t,
         const float* __restrict__ cst, float* __restrict__ v)
{
    const int wid = threadIdx.x >> 5, lane = threadIdx.x & 31;
    const long j = (long)blockIdx.x * 8 + wid;
    const float4* xr = (const float4*)(x + j * DIM);
    const float4* tr = (const float4*)t;
    float acc = 0.f;
    #pragma unroll
    for (int i = 0; i < 8; i++) {
        float4 a = xr[lane + 32 * i];
        float4 b = tr[lane + 32 * i];
        acc += a.x * b.x + a.y * b.y + a.z * b.z + a.w * b.w;
    }
    #pragma unroll
    for (int o = 16; o > 0; o >>= 1) acc += __shfl_xor_sync(0xffffffffu, acc, o);
    if (lane == 0) v[j] = (acc + cst[0]) * (1.0f / 32.0f);
}

// ---------------------------------------------------------------------------
// Row softmax of (S + v[col]) fused with hi/lo split of probabilities.
// v carries the bq-dependent column term (already scaled by 1/32).
// ---------------------------------------------------------------------------
__global__ void __launch_bounds__(256)
softmax_split_kernel(const float* __restrict__ S, const float* __restrict__ Vv,
                     __nv_bfloat16* __restrict__ Ahi,
                     __nv_bfloat16* __restrict__ Alo)
{
    __shared__ float red[8];
    __shared__ float bcast;

    const long row = blockIdx.x;
    const float4* p4 = (const float4*)(S + row * (long)SEQ);
    const float4* vp = (const float4*)(Vv + (row & ~(long)(SEQ - 1)));
    const int tid  = threadIdx.x;
    const int lane = tid & 31;
    const int wid  = tid >> 5;

    float4 v0 = p4[tid];
    float4 v1 = p4[tid + 256];
    float4 a0 = vp[tid];
    float4 a1 = vp[tid + 256];
    v0.x += a0.x; v0.y += a0.y; v0.z += a0.z; v0.w += a0.w;
    v1.x += a1.x; v1.y += a1.y; v1.z += a1.z; v1.w += a1.w;

    float m = fmaxf(fmaxf(fmaxf(v0.x, v0.y), fmaxf(v0.z, v0.w)),
                    fmaxf(fmaxf(v1.x, v1.y), fmaxf(v1.z, v1.w)));
    #pragma unroll
    for (int o = 16; o > 0; o >>= 1) m = fmaxf(m, __shfl_xor_sync(0xffffffffu, m, o));
    if (lane == 0) red[wid] = m;
    __syncthreads();
    if (wid == 0) {
        float x = (lane < 8) ? red[lane] : -3.4e38f;
        #pragma unroll
        for (int o = 4; o > 0; o >>= 1) x = fmaxf(x, __shfl_xor_sync(0xffffffffu, x, o));
        if (lane == 0) bcast = x;
    }
    __syncthreads();
    m = bcast;
    __syncthreads();

    v0.x = __expf(v0.x - m); v0.y = __expf(v0.y - m);
    v0.z = __expf(v0.z - m); v0.w = __expf(v0.w - m);
    v1.x = __expf(v1.x - m); v1.y = __expf(v1.y - m);
    v1.z = __expf(v1.z - m); v1.w = __expf(v1.w - m);
    float s = (v0.x + v0.y + v0.z + v0.w) + (v1.x + v1.y + v1.z + v1.w);
    #pragma unroll
    for (int o = 16; o > 0; o >>= 1) s += __shfl_xor_sync(0xffffffffu, s, o);
    if (lane == 0) red[wid] = s;
    __syncthreads();
    if (wid == 0) {
        float x = (lane < 8) ? red[lane] : 0.0f;
        #pragma unroll
        for (int o = 4; o > 0; o >>= 1) x += __shfl_xor_sync(0xffffffffu, x, o);
        if (lane == 0) bcast = x;
    }
    __syncthreads();
    const float inv = 1.0f / bcast;

    v0.x *= inv; v0.y *= inv; v0.z *= inv; v0.w *= inv;
    v1.x *= inv; v1.y *= inv; v1.z *= inv; v1.w *= inv;

    const long base = row * (long)SEQ;
    split_store4(Ahi, Alo, base + tid * 4, v0);
    split_store4(Ahi, Alo, base + 1024 + tid * 4, v1);
}

// ---------------------------------------------------------------------------
// kernel_launch
// inputs: x, Wq, bq, Wk, bk, Wv, bv
//
// Algebra: softmax is row-shift invariant, so
//   scores = (x Wq^T + bq)(x Wk^T + bk)^T / 32
//          ~ x (Wq^T Wk) x^T / 32 + 1 v^T   (row-constant terms dropped)
//   with v_j = (x_j . (Wk^T bq) + bq.bk)/32.
// This removes the K projection GEMM entirely.
// out = attn . (x Wv^T + bv)  (V path unchanged).
// ---------------------------------------------------------------------------
extern "C" void kernel_launch(void* const* d_in, const int* in_sizes, int n_in,
                              void* d_out, int out_size)
{
    const float* x  = (const float*)d_in[0];
    const float* Wq = (const float*)d_in[1];
    const float* bq = (const float*)d_in[2];
    const float* Wk = (const float*)d_in[3];
    const float* bk = (const float*)d_in[4];
    const float* Wv = (const float*)d_in[5];
    const float* bv = (const float*)d_in[6];
    float* out = (float*)d_out;

    __nv_bfloat16 *xhi, *xlo, *wvhi, *wvlo, *wqthi, *wqtlo, *wkthi, *wktlo;
    __nv_bfloat16 *mthi, *mtlo, *phi, *plo, *vthi, *vtlo, *ahi, *alo;
    float *sc, *tvec, *cst, *vrow, *zero;
    cudaGetSymbolAddress((void**)&xhi,   g_xhi);
    cudaGetSymbolAddress((void**)&xlo,   g_xlo);
    cudaGetSymbolAddress((void**)&wvhi,  g_wvhi);
    cudaGetSymbolAddress((void**)&wvlo,  g_wvlo);
    cudaGetSymbolAddress((void**)&wqthi, g_wqthi);
    cudaGetSymbolAddress((void**)&wqtlo, g_wqtlo);
    cudaGetSymbolAddress((void**)&wkthi, g_wkthi);
    cudaGetSymbolAddress((void**)&wktlo, g_wktlo);
    cudaGetSymbolAddress((void**)&mthi,  g_mthi);
    cudaGetSymbolAddress((void**)&mtlo,  g_mtlo);
    cudaGetSymbolAddress((void**)&phi,   g_phi);
    cudaGetSymbolAddress((void**)&plo,   g_plo);
    cudaGetSymbolAddress((void**)&vthi,  g_vthi);
    cudaGetSymbolAddress((void**)&vtlo,  g_vtlo);
    cudaGetSymbolAddress((void**)&sc,    g_s);
    cudaGetSymbolAddress((void**)&ahi,   g_ahi);
    cudaGetSymbolAddress((void**)&alo,   g_alo);
    cudaGetSymbolAddress((void**)&tvec,  g_tvec);
    cudaGetSymbolAddress((void**)&cst,   g_cst);
    cudaGetSymbolAddress((void**)&vrow,  g_vrow);
    cudaGetSymbolAddress((void**)&zero,  g_zero);

    cudaFuncSetAttribute(gemm_bf16x3<0>, cudaFuncAttributeMaxDynamicSharedMemorySize, SMEM_TOTAL);
    cudaFuncSetAttribute(gemm_bf16x3<1>, cudaFuncAttributeMaxDynamicSharedMemorySize, SMEM_TOTAL);
    cudaFuncSetAttribute(gemm_bf16x3<2>, cudaFuncAttributeMaxDynamicSharedMemorySize, SMEM_TOTAL);

    const long nxd = (long)NROWS * DIM;
    const long nww = (long)DIM * DIM;

    // pre-passes
    split_kernel<<<(int)(nxd / 4 / 256), 256>>>(x,  xhi,  xlo,  nxd);
    split_kernel<<<(int)(nww / 4 / 256), 256>>>(Wv, wvhi, wvlo, nww);
    {
        dim3 grid(DIM / 32, DIM / 32);
        dim3 blk(32, 8);
        transpose_split_kernel<<<grid, blk>>>(Wq, wqthi, wqtlo, DIM, DIM);
        transpose_split_kernel<<<grid, blk>>>(Wk, wkthi, wktlo, DIM, DIM);
    }
    t_kernel<<<DIM / 256, 256>>>(Wk, bq, bk, tvec, cst);
    v_kernel<<<NROWS / 8, 256>>>(x, tvec, cst, vrow);

    // Mt[d',d] = sum_e Wk[e,d'] Wq[e,d] : A = Wk^T, B = Wq^T -> split out
    {
        dim3 grid(DIM / 128, DIM / 128, 1);
        gemm_bf16x3<1><<<grid, 256, SMEM_TOTAL>>>(wkthi, wktlo, wqthi, wqtlo, zero,
                                                  nullptr, mthi, mtlo,
                                                  DIM, DIM, DIM, DIM, 0, 0, 0, 1.0f);
    }
    // P[s,d'] = sum_d x[s,d] Mt[d',d] -> split out
    {
        dim3 grid(NROWS / 128, DIM / 128, 1);
        gemm_bf16x3<1><<<grid, 256, SMEM_TOTAL>>>(xhi, xlo, mthi, mtlo, zero,
                                                  nullptr, phi, plo,
                                                  DIM, DIM, DIM, DIM, 0, 0, 0, 1.0f);
    }
    // Vt[d,s] = sum_k Wv[d,k] x[s,k] + bv[d] (row bias) -> split out, [D, B*S]
    {
        dim3 grid(DIM / 128, NROWS / 128, 1);
        gemm_bf16x3<2><<<grid, 256, SMEM_TOTAL>>>(wvhi, wvlo, xhi, xlo, bv,
                                                  nullptr, vthi, vtlo,
                                                  DIM, DIM, DIM, NROWS, 0, 0, 0, 1.0f);
    }
    // scores: per batch  P[2048,1024] x x[2048,1024]^T * 1/32 -> fp32
    {
        dim3 grid(SEQ / 128, SEQ / 128, BATCH);
        gemm_bf16x3<0><<<grid, 256, SMEM_TOTAL>>>(phi, plo, xhi, xlo, nullptr,
                                                  sc, nullptr, nullptr,
                                                  DIM, DIM, DIM, SEQ,
                                                  (long)SEQ * DIM, (long)SEQ * DIM,
                                                  (long)SEQ * SEQ, 1.0f / 32.0f);
    }
    // softmax(scores + v[col]) + split attn
    softmax_split_kernel<<<NROWS, 256>>>(sc, vrow, ahi, alo);

    // out: per batch attn[2048,2048] x Vt[:, b*2048 : (b+1)*2048]^T -> fp32
    {
        dim3 grid(SEQ / 128, DIM / 128, BATCH);
        gemm_bf16x3<0><<<grid, 256, SMEM_TOTAL>>>(ahi, alo, vthi, vtlo, nullptr,
                                                  out, nullptr, nullptr,
                                                  SEQ, SEQ, NROWS, DIM,
                                                  (long)SEQ * SEQ, (long)SEQ,
                                                  (long)SEQ * DIM, 1.0f);
    }
}

// round 14
// speedup vs baseline: 1.1532x; 1.0362x over previous
#include <cuda_runtime.h>
#include <cuda_bf16.h>
#include <stdint.h>
#include <math.h>

// ---------------------------------------------------------------------------
// Problem constants
// ---------------------------------------------------------------------------
#define BATCH 4
#define SEQ   2048
#define DIM   1024
#define NROWS (BATCH * SEQ)          // 8192

// ---------------------------------------------------------------------------
// Scratch (device globals: allocation-free; zero-initialized by CUDA)
// ---------------------------------------------------------------------------
__device__ __align__(128) __nv_bfloat16 g_xhi[(size_t)NROWS * DIM];
__device__ __align__(128) __nv_bfloat16 g_xlo[(size_t)NROWS * DIM];
__device__ __align__(128) __nv_bfloat16 g_wvhi[(size_t)DIM * DIM];
__device__ __align__(128) __nv_bfloat16 g_wvlo[(size_t)DIM * DIM];
__device__ __align__(128) __nv_bfloat16 g_wqthi[(size_t)DIM * DIM];  // Wq^T split
__device__ __align__(128) __nv_bfloat16 g_wqtlo[(size_t)DIM * DIM];
__device__ __align__(128) __nv_bfloat16 g_wkthi[(size_t)DIM * DIM];  // Wk^T split
__device__ __align__(128) __nv_bfloat16 g_wktlo[(size_t)DIM * DIM];
__device__ __align__(128) __nv_bfloat16 g_mthi[(size_t)DIM * DIM];   // Mt = (Wq^T Wk)^T
__device__ __align__(128) __nv_bfloat16 g_mtlo[(size_t)DIM * DIM];
__device__ __align__(128) __nv_bfloat16 g_phi[(size_t)NROWS * DIM];  // P = x M
__device__ __align__(128) __nv_bfloat16 g_plo[(size_t)NROWS * DIM];
__device__ __align__(128) __nv_bfloat16 g_vthi[(size_t)DIM * NROWS]; // Vt [D, B*S]
__device__ __align__(128) __nv_bfloat16 g_vtlo[(size_t)DIM * NROWS];
__device__ __align__(128) float         g_s[(size_t)BATCH * SEQ * SEQ];
__device__ __align__(128) __nv_bfloat16 g_ahi[(size_t)BATCH * SEQ * SEQ];
__device__ __align__(128) __nv_bfloat16 g_alo[(size_t)BATCH * SEQ * SEQ];
__device__ __align__(128) float         g_tvec[DIM];      // t = Wk^T bq
__device__ __align__(128) float         g_cst[1];         // bq . bk
__device__ __align__(128) float         g_vrow[NROWS];    // v_j (pre-scaled 1/32)
__device__ __align__(128) float         g_zero[DIM];      // zero bias (never written)

// ---------------------------------------------------------------------------
// PTX helpers (baseline PTX only — NO tcgen05: harness ptxas targets sm_103)
// ---------------------------------------------------------------------------
__device__ __forceinline__ uint32_t smem_u32(const void* p) {
    uint32_t a;
    asm("{ .reg .u64 t; cvta.to.shared.u64 t, %1; cvt.u32.u64 %0, t; }"
        : "=r"(a) : "l"(p));
    return a;
}

__device__ __forceinline__ void ldmatrix_x4(uint32_t& r0, uint32_t& r1,
                                            uint32_t& r2, uint32_t& r3,
                                            uint32_t addr) {
    asm volatile("ldmatrix.sync.aligned.m8n8.x4.shared.b16 {%0,%1,%2,%3}, [%4];"
                 : "=r"(r0), "=r"(r1), "=r"(r2), "=r"(r3) : "r"(addr));
}

__device__ __forceinline__ void mma_bf16(float* d, const uint32_t* a,
                                         const uint32_t* b) {
    asm volatile(
        "mma.sync.aligned.m16n8k16.row.col.f32.bf16.bf16.f32 "
        "{%0,%1,%2,%3}, {%4,%5,%6,%7}, {%8,%9}, {%0,%1,%2,%3};"
        : "+f"(d[0]), "+f"(d[1]), "+f"(d[2]), "+f"(d[3])
        : "r"(a[0]), "r"(a[1]), "r"(a[2]), "r"(a[3]),
          "r"(b[0]), "r"(b[1]));
}

#define CP_ASYNC16(smem, gptr) \
    asm volatile("cp.async.cg.shared.global [%0], [%1], 16;" \
                 :: "r"(smem), "l"(gptr) : "memory")
#define CP_COMMIT() asm volatile("cp.async.commit_group;" ::: "memory")
#define CP_WAIT(n)  asm volatile("cp.async.wait_group %0;" :: "n"(n) : "memory")

__device__ __forceinline__ void split2_store(__nv_bfloat16* hi, __nv_bfloat16* lo,
                                             long idx, float v0, float v1)
{
    __nv_bfloat16 h0 = __float2bfloat16(v0);
    __nv_bfloat16 h1 = __float2bfloat16(v1);
    *(__nv_bfloat162*)(hi + idx) = __halves2bfloat162(h0, h1);
    *(__nv_bfloat162*)(lo + idx) = __halves2bfloat162(
        __float2bfloat16(v0 - __bfloat162float(h0)),
        __float2bfloat16(v1 - __bfloat162float(h1)));
}

// ---------------------------------------------------------------------------
// bf16x3 GEMM via mma.sync + cp.async 3-stage pipeline, BK=64.
//   C[m,n] = alpha * sum_k A[m,k]*B[n,k] (+ bias)
//   A ~ Ahi+Alo rm [M,K] lda; B ~ Bhi+Blo rm [N,K] ldb; K logically tripled
//   via segments (hi,hi),(hi,lo),(lo,hi) into one fp32 accumulator.
//   Tile 128x128, BK=64, 128 thr = 4 warps (2m x 2n), warp tile 64x64
//   (square warp tile halves smem read duplication: 128 B/HMMA).
//   smem rows padded to 72 elems (144B = 9*16B): aligned + conflict-free.
// EPI: 0 = fp32 out (alpha, no bias)
//      1 = bf16 hi/lo split out, column bias
//      2 = bf16 hi/lo split out, row bias
// ---------------------------------------------------------------------------
#define PAD    72
#define SMB    (128 * PAD * 2)          // 18432 bytes per stage per matrix
#define NSTAGE 3
#define SMEM_TOTAL (2 * NSTAGE * SMB)   // 110592

template <int EPI>
__global__ void __launch_bounds__(128, 2)
gemm_bf16x3(const __nv_bfloat16* __restrict__ Ahi, const __nv_bfloat16* __restrict__ Alo,
            const __nv_bfloat16* __restrict__ Bhi, const __nv_bfloat16* __restrict__ Blo,
            const float* __restrict__ bias,
            float* __restrict__ Cf,
            __nv_bfloat16* __restrict__ Chi, __nv_bfloat16* __restrict__ Clo,
            int K, int lda, int ldb, int ldc,
            long sA, long sB, long sC, float alpha)
{
    extern __shared__ __align__(128) char dsm[];
    const uint32_t sa_base = smem_u32(dsm);
    const uint32_t sb_base = sa_base + NSTAGE * SMB;

    const int tid  = threadIdx.x;
    const int lane = tid & 31;
    const int wid  = tid >> 5;
    const int wm   = (wid >> 1) * 64;   // warp m origin (0 or 64)
    const int wn   = (wid & 1) * 64;    // warp n origin (0 or 64)

    const long m0 = (long)blockIdx.x * 128;
    const long n0 = (long)blockIdx.y * 128;
    const int  z  = blockIdx.z;
    const int  KT = K >> 6;             // 64-wide K tiles per segment
    const int  NT = 3 * KT;

    const __nv_bfloat16* Ah = Ahi + (long)z * sA;
    const __nv_bfloat16* Al = Alo + (long)z * sA;
    const __nv_bfloat16* Bh = Bhi + (long)z * sB;
    const __nv_bfloat16* Bl = Blo + (long)z * sB;

    float acc[4][8][4];
    #pragma unroll
    for (int i = 0; i < 4; i++)
        #pragma unroll
        for (int j = 0; j < 8; j++)
            #pragma unroll
            for (int r = 0; r < 4; r++) acc[i][j][r] = 0.0f;

    auto issue_tile = [&](int t, int buf) {
        const int seg = t / KT;
        const long kk = (long)(t - seg * KT) << 6;
        const __nv_bfloat16* Ap = (seg < 2)  ? Ah : Al;
        const __nv_bfloat16* Bp = (seg != 1) ? Bh : Bl;
        const uint32_t sa = sa_base + buf * SMB;
        const uint32_t sb = sb_base + buf * SMB;
        #pragma unroll
        for (int i = 0; i < 8; i++) {
            const int c   = tid + i * 128;     // 0..1023
            const int row = c >> 3;            // 0..127
            const int j   = c & 7;             // 16B chunk within 64 k
            const uint32_t so = (uint32_t)(row * PAD + j * 8) * 2;
            CP_ASYNC16(sa + so, Ap + (m0 + row) * (long)lda + kk + j * 8);
            CP_ASYNC16(sb + so, Bp + (n0 + row) * (long)ldb + kk + j * 8);
        }
        CP_COMMIT();
    };

    auto compute = [&](int buf) {
        const uint32_t ab = sa_base + buf * SMB;
        const uint32_t bb = sb_base + buf * SMB;
        #pragma unroll
        for (int ks = 0; ks < 4; ks++) {
            uint32_t af[4][4], bf[8][2];
            #pragma unroll
            for (int mt = 0; mt < 4; mt++) {
                const int row  = wm + mt * 16 + (lane & 15);
                const int koff = ks * 16 + ((lane >> 4) << 3);
                ldmatrix_x4(af[mt][0], af[mt][1], af[mt][2], af[mt][3],
                            ab + (row * PAD + koff) * 2);
            }
            #pragma unroll
            for (int h = 0; h < 4; h++) {
                const int row  = wn + h * 16 + (lane & 7) + ((lane >> 4) << 3);
                const int koff = ks * 16 + ((lane >> 3) & 1) * 8;
                ldmatrix_x4(bf[h * 2][0], bf[h * 2][1],
                            bf[h * 2 + 1][0], bf[h * 2 + 1][1],
                            bb + (row * PAD + koff) * 2);
            }
            #pragma unroll
            for (int mt = 0; mt < 4; mt++)
                #pragma unroll
                for (int nt = 0; nt < 8; nt++)
                    mma_bf16(acc[mt][nt], af[mt], bf[nt]);
        }
    };

    // 3-stage pipeline, one barrier per BK=64 iteration.
    issue_tile(0, 0);
    issue_tile(1, 1);
    for (int t = 0; t < NT; t++) {
        CP_WAIT(1);                 // group t complete
        __syncthreads();
        if (t + 2 < NT) issue_tile(t + 2, (t + 2) % 3);   // overwrites buf read at t-1
        compute(t % 3);
    }

    // epilogue
    const int g   = lane >> 2;
    const int tg2 = (lane & 3) * 2;
    #pragma unroll
    for (int mt = 0; mt < 4; mt++) {
        #pragma unroll
        for (int half = 0; half < 2; half++) {
            const long row = m0 + wm + mt * 16 + g + half * 8;
            const long rbase = (long)z * sC + row * (long)ldc;
            #pragma unroll
            for (int nt = 0; nt < 8; nt++) {
                const long col = n0 + wn + nt * 8 + tg2;
                float v0 = acc[mt][nt][half * 2 + 0] * alpha;
                float v1 = acc[mt][nt][half * 2 + 1] * alpha;
                if (EPI == 0) {
                    *(float2*)(Cf + rbase + col) = make_float2(v0, v1);
                } else if (EPI == 1) {
                    v0 += bias[col];
                    v1 += bias[col + 1];
                    split2_store(Chi, Clo, rbase + col, v0, v1);
                } else {
                    const float b = bias[row];
                    split2_store(Chi, Clo, rbase + col, v0 + b, v1 + b);
                }
            }
        }
    }
}

// ---------------------------------------------------------------------------
// fp32 -> bf16 hi/lo split
// ---------------------------------------------------------------------------
__device__ __forceinline__ void split_store4(__nv_bfloat16* hi, __nv_bfloat16* lo,
                                             long idx, float4 v)
{
    split2_store(hi, lo, idx,     v.x, v.y);
    split2_store(hi, lo, idx + 2, v.z, v.w);
}

__global__ void __launch_bounds__(256)
split_kernel(const float* __restrict__ in, __nv_bfloat16* __restrict__ hi,
             __nv_bfloat16* __restrict__ lo, long n)
{
    long i = ((long)blockIdx.x * 256 + threadIdx.x) * 4;
    if (i >= n) return;
    float4 f = *(const float4*)(in + i);
    split_store4(hi, lo, i, f);
}

// Generic transpose + split: in [R, C] fp32 -> out [C, R] bf16 hi/lo
__global__ void __launch_bounds__(256)
transpose_split_kernel(const float* __restrict__ in,
                       __nv_bfloat16* __restrict__ oh,
                       __nv_bfloat16* __restrict__ ol, int R, int C)
{
    __shared__ float t[32][33];
    const int r0 = blockIdx.y * 32;
    const int c0 = blockIdx.x * 32;
    const int tx = threadIdx.x, ty = threadIdx.y;

    #pragma unroll
    for (int j = 0; j < 4; j++)
        t[ty + 8 * j][tx] = in[(long)(r0 + ty + 8 * j) * C + c0 + tx];
    __syncthreads();
    #pragma unroll
    for (int j = 0; j < 4; j++) {
        float val = t[tx][ty + 8 * j];
        long o = (long)(c0 + ty + 8 * j) * R + r0 + tx;
        __nv_bfloat16 h = __float2bfloat16(val);
        oh[o] = h;
        ol[o] = __float2bfloat16(val - __bfloat162float(h));
    }
}

// ---------------------------------------------------------------------------
// t = Wk^T bq (t_d = sum_e bq[e] * Wk[e,d]); also c = bq . bk (block 0)
// ---------------------------------------------------------------------------
__global__ void __launch_bounds__(256)
t_kernel(const float* __restrict__ Wk, const float* __restrict__ bq,
         const float* __restrict__ bk, float* __restrict__ t,
         float* __restrict__ cst)
{
    const int d = blockIdx.x * 256 + threadIdx.x;
    float a0 = 0.f, a1 = 0.f, a2 = 0.f, a3 = 0.f;
    for (int e = 0; e < DIM; e += 4) {
        a0 += bq[e]     * Wk[(long)e * DIM + d];
        a1 += bq[e + 1] * Wk[(long)(e + 1) * DIM + d];
        a2 += bq[e + 2] * Wk[(long)(e + 2) * DIM + d];
        a3 += bq[e + 3] * Wk[(long)(e + 3) * DIM + d];
    }
    t[d] = (a0 + a1) + (a2 + a3);

    if (blockIdx.x == 0) {
        float c = 0.f;
        for (int e = threadIdx.x; e < DIM; e += 256) c += bq[e] * bk[e];
        __shared__ float red[8];
        const int lane = threadIdx.x & 31, wid = threadIdx.x >> 5;
        #pragma unroll
        for (int o = 16; o > 0; o >>= 1) c += __shfl_xor_sync(0xffffffffu, c, o);
        if (lane == 0) red[wid] = c;
        __syncthreads();
        if (threadIdx.x == 0) {
            float s = 0.f;
            #pragma unroll
            for (int w = 0; w < 8; w++) s += red[w];
            cst[0] = s;
        }
    }
}

// ---------------------------------------------------------------------------
// v_j = (x_j . t + c) / 32      (one warp per row)
// ---------------------------------------------------------------------------
__global__ void __launch_bounds__(256)
v_kernel(const float* __restrict__ x, const float* __restrict__ t,
         const float* __restrict__ cst, float* __restrict__ v)
{
    const int wid = threadIdx.x >> 5, lane = threadIdx.x & 31;
    const long j = (long)blockIdx.x * 8 + wid;
    const float4* xr = (const float4*)(x + j * DIM);
    const float4* tr = (const float4*)t;
    float acc = 0.f;
    #pragma unroll
    for (int i = 0; i < 8; i++) {
        float4 a = xr[lane + 32 * i];
        float4 b = tr[lane + 32 * i];
        acc += a.x * b.x + a.y * b.y + a.z * b.z + a.w * b.w;
    }
    #pragma unroll
    for (int o = 16; o > 0; o >>= 1) acc += __shfl_xor_sync(0xffffffffu, acc, o);
    if (lane == 0) v[j] = (acc + cst[0]) * (1.0f / 32.0f);
}

// ---------------------------------------------------------------------------
// Row softmax of (S + v[col]) fused with hi/lo split of probabilities.
// ---------------------------------------------------------------------------
__global__ void __launch_bounds__(256)
softmax_split_kernel(const float* __restrict__ S, const float* __restrict__ Vv,
                     __nv_bfloat16* __restrict__ Ahi,
                     __nv_bfloat16* __restrict__ Alo)
{
    __shared__ float red[8];
    __shared__ float bcast;

    const long row = blockIdx.x;
    const float4* p4 = (const float4*)(S + row * (long)SEQ);
    const float4* vp = (const float4*)(Vv + (row & ~(long)(SEQ - 1)));
    const int tid  = threadIdx.x;
    const int lane = tid & 31;
    const int wid  = tid >> 5;

    float4 v0 = p4[tid];
    float4 v1 = p4[tid + 256];
    float4 a0 = vp[tid];
    float4 a1 = vp[tid + 256];
    v0.x += a0.x; v0.y += a0.y; v0.z += a0.z; v0.w += a0.w;
    v1.x += a1.x; v1.y += a1.y; v1.z += a1.z; v1.w += a1.w;

    float m = fmaxf(fmaxf(fmaxf(v0.x, v0.y), fmaxf(v0.z, v0.w)),
                    fmaxf(fmaxf(v1.x, v1.y), fmaxf(v1.z, v1.w)));
    #pragma unroll
    for (int o = 16; o > 0; o >>= 1) m = fmaxf(m, __shfl_xor_sync(0xffffffffu, m, o));
    if (lane == 0) red[wid] = m;
    __syncthreads();
    if (wid == 0) {
        float x = (lane < 8) ? red[lane] : -3.4e38f;
        #pragma unroll
        for (int o = 4; o > 0; o >>= 1) x = fmaxf(x, __shfl_xor_sync(0xffffffffu, x, o));
        if (lane == 0) bcast = x;
    }
    __syncthreads();
    m = bcast;
    __syncthreads();

    v0.x = __expf(v0.x - m); v0.y = __expf(v0.y - m);
    v0.z = __expf(v0.z - m); v0.w = __expf(v0.w - m);
    v1.x = __expf(v1.x - m); v1.y = __expf(v1.y - m);
    v1.z = __expf(v1.z - m); v1.w = __expf(v1.w - m);
    float s = (v0.x + v0.y + v0.z + v0.w) + (v1.x + v1.y + v1.z + v1.w);
    #pragma unroll
    for (int o = 16; o > 0; o >>= 1) s += __shfl_xor_sync(0xffffffffu, s, o);
    if (lane == 0) red[wid] = s;
    __syncthreads();
    if (wid == 0) {
        float x = (lane < 8) ? red[lane] : 0.0f;
        #pragma unroll
        for (int o = 4; o > 0; o >>= 1) x += __shfl_xor_sync(0xffffffffu, x, o);
        if (lane == 0) bcast = x;
    }
    __syncthreads();
    const float inv = 1.0f / bcast;

    v0.x *= inv; v0.y *= inv; v0.z *= inv; v0.w *= inv;
    v1.x *= inv; v1.y *= inv; v1.z *= inv; v1.w *= inv;

    const long base = row * (long)SEQ;
    split_store4(Ahi, Alo, base + tid * 4, v0);
    split_store4(Ahi, Alo, base + 1024 + tid * 4, v1);
}

// ---------------------------------------------------------------------------
// kernel_launch
// inputs: x, Wq, bq, Wk, bk, Wv, bv
//
// Algebra: softmax is row-shift invariant, so
//   scores = (x Wq^T + bq)(x Wk^T + bk)^T / 32
//          ~ x (Wq^T Wk) x^T / 32 + 1 v^T   (row-constant terms dropped)
//   with v_j = (x_j . (Wk^T bq) + bq.bk)/32.
// out = attn . (x Wv^T + bv).
// ---------------------------------------------------------------------------
extern "C" void kernel_launch(void* const* d_in, const int* in_sizes, int n_in,
                              void* d_out, int out_size)
{
    const float* x  = (const float*)d_in[0];
    const float* Wq = (const float*)d_in[1];
    const float* bq = (const float*)d_in[2];
    const float* Wk = (const float*)d_in[3];
    const float* bk = (const float*)d_in[4];
    const float* Wv = (const float*)d_in[5];
    const float* bv = (const float*)d_in[6];
    float* out = (float*)d_out;

    __nv_bfloat16 *xhi, *xlo, *wvhi, *wvlo, *wqthi, *wqtlo, *wkthi, *wktlo;
    __nv_bfloat16 *mthi, *mtlo, *phi, *plo, *vthi, *vtlo, *ahi, *alo;
    float *sc, *tvec, *cst, *vrow, *zero;
    cudaGetSymbolAddress((void**)&xhi,   g_xhi);
    cudaGetSymbolAddress((void**)&xlo,   g_xlo);
    cudaGetSymbolAddress((void**)&wvhi,  g_wvhi);
    cudaGetSymbolAddress((void**)&wvlo,  g_wvlo);
    cudaGetSymbolAddress((void**)&wqthi, g_wqthi);
    cudaGetSymbolAddress((void**)&wqtlo, g_wqtlo);
    cudaGetSymbolAddress((void**)&wkthi, g_wkthi);
    cudaGetSymbolAddress((void**)&wktlo, g_wktlo);
    cudaGetSymbolAddress((void**)&mthi,  g_mthi);
    cudaGetSymbolAddress((void**)&mtlo,  g_mtlo);
    cudaGetSymbolAddress((void**)&phi,   g_phi);
    cudaGetSymbolAddress((void**)&plo,   g_plo);
    cudaGetSymbolAddress((void**)&vthi,  g_vthi);
    cudaGetSymbolAddress((void**)&vtlo,  g_vtlo);
    cudaGetSymbolAddress((void**)&sc,    g_s);
    cudaGetSymbolAddress((void**)&ahi,   g_ahi);
    cudaGetSymbolAddress((void**)&alo,   g_alo);
    cudaGetSymbolAddress((void**)&tvec,  g_tvec);
    cudaGetSymbolAddress((void**)&cst,   g_cst);
    cudaGetSymbolAddress((void**)&vrow,  g_vrow);
    cudaGetSymbolAddress((void**)&zero,  g_zero);

    cudaFuncSetAttribute(gemm_bf16x3<0>, cudaFuncAttributeMaxDynamicSharedMemorySize, SMEM_TOTAL);
    cudaFuncSetAttribute(gemm_bf16x3<1>, cudaFuncAttributeMaxDynamicSharedMemorySize, SMEM_TOTAL);
    cudaFuncSetAttribute(gemm_bf16x3<2>, cudaFuncAttributeMaxDynamicSharedMemorySize, SMEM_TOTAL);

    const long nxd = (long)NROWS * DIM;
    const long nww = (long)DIM * DIM;

    // pre-passes
    split_kernel<<<(int)(nxd / 4 / 256), 256>>>(x,  xhi,  xlo,  nxd);
    split_kernel<<<(int)(nww / 4 / 256), 256>>>(Wv, wvhi, wvlo, nww);
    {
        dim3 grid(DIM / 32, DIM / 32);
        dim3 blk(32, 8);
        transpose_split_kernel<<<grid, blk>>>(Wq, wqthi, wqtlo, DIM, DIM);
        transpose_split_kernel<<<grid, blk>>>(Wk, wkthi, wktlo, DIM, DIM);
    }
    t_kernel<<<DIM / 256, 256>>>(Wk, bq, bk, tvec, cst);
    v_kernel<<<NROWS / 8, 256>>>(x, tvec, cst, vrow);

    // Mt[d',d] = sum_e Wk[e,d'] Wq[e,d] -> split out
    {
        dim3 grid(DIM / 128, DIM / 128, 1);
        gemm_bf16x3<1><<<grid, 128, SMEM_TOTAL>>>(wkthi, wktlo, wqthi, wqtlo, zero,
                                                  nullptr, mthi, mtlo,
                                                  DIM, DIM, DIM, DIM, 0, 0, 0, 1.0f);
    }
    // P[s,d'] = sum_d x[s,d] Mt[d',d] -> split out
    {
        dim3 grid(NROWS / 128, DIM / 128, 1);
        gemm_bf16x3<1><<<grid, 128, SMEM_TOTAL>>>(xhi, xlo, mthi, mtlo, zero,
                                                  nullptr, phi, plo,
                                                  DIM, DIM, DIM, DIM, 0, 0, 0, 1.0f);
    }
    // Vt[d,s] = sum_k Wv[d,k] x[s,k] + bv[d] (row bias) -> split out, [D, B*S]
    {
        dim3 grid(DIM / 128, NROWS / 128, 1);
        gemm_bf16x3<2><<<grid, 128, SMEM_TOTAL>>>(wvhi, wvlo, xhi, xlo, bv,
                                                  nullptr, vthi, vtlo,
                                                  DIM, DIM, DIM, NROWS, 0, 0, 0, 1.0f);
    }
    // scores: per batch  P[2048,1024] x x[2048,1024]^T * 1/32 -> fp32
    {
        dim3 grid(SEQ / 128, SEQ / 128, BATCH);
        gemm_bf16x3<0><<<grid, 128, SMEM_TOTAL>>>(phi, plo, xhi, xlo, nullptr,
                                                  sc, nullptr, nullptr,
                                                  DIM, DIM, DIM, SEQ,
                                                  (long)SEQ * DIM, (long)SEQ * DIM,
                                                  (long)SEQ * SEQ, 1.0f / 32.0f);
    }
    // softmax(scores + v[col]) + split attn
    softmax_split_kernel<<<NROWS, 256>>>(sc, vrow, ahi, alo);

    // out: per batch attn[2048,2048] x Vt[:, b*2048 : (b+1)*2048]^T -> fp32
    {
        dim3 grid(SEQ / 128, DIM / 128, BATCH);
        gemm_bf16x3<0><<<grid, 128, SMEM_TOTAL>>>(ahi, alo, vthi, vtlo, nullptr,
                                                  out, nullptr, nullptr,
                                                  SEQ, SEQ, NROWS, DIM,
                                                  (long)SEQ * SEQ, (long)SEQ,
                                                  (long)SEQ * DIM, 1.0f);
    }
}

// round 15
// speedup vs baseline: 1.1885x; 1.0307x over previous
#include <cuda_runtime.h>
#include <cuda_bf16.h>
#include <stdint.h>
#include <math.h>

// ---------------------------------------------------------------------------
// Problem constants
// ---------------------------------------------------------------------------
#define BATCH 4
#define SEQ   2048
#define DIM   1024
#define NROWS (BATCH * SEQ)          // 8192

// ---------------------------------------------------------------------------
// Scratch (device globals: allocation-free; zero-initialized by CUDA)
// ---------------------------------------------------------------------------
__device__ __align__(128) __nv_bfloat16 g_xhi[(size_t)NROWS * DIM];
__device__ __align__(128) __nv_bfloat16 g_xlo[(size_t)NROWS * DIM];
__device__ __align__(128) __nv_bfloat16 g_wvhi[(size_t)DIM * DIM];
__device__ __align__(128) __nv_bfloat16 g_wvlo[(size_t)DIM * DIM];
__device__ __align__(128) __nv_bfloat16 g_wqthi[(size_t)DIM * DIM];  // Wq^T split
__device__ __align__(128) __nv_bfloat16 g_wqtlo[(size_t)DIM * DIM];
__device__ __align__(128) __nv_bfloat16 g_wkthi[(size_t)DIM * DIM];  // Wk^T split
__device__ __align__(128) __nv_bfloat16 g_wktlo[(size_t)DIM * DIM];
__device__ __align__(128) __nv_bfloat16 g_mthi[(size_t)DIM * DIM];   // Mt = (Wq^T Wk)^T
__device__ __align__(128) __nv_bfloat16 g_mtlo[(size_t)DIM * DIM];
__device__ __align__(128) __nv_bfloat16 g_phi[(size_t)NROWS * DIM];  // P = x M
__device__ __align__(128) __nv_bfloat16 g_plo[(size_t)NROWS * DIM];
__device__ __align__(128) __nv_bfloat16 g_vthi[(size_t)DIM * NROWS]; // Vt [D, B*S]
__device__ __align__(128) __nv_bfloat16 g_vtlo[(size_t)DIM * NROWS];
__device__ __align__(128) float         g_s[(size_t)BATCH * SEQ * SEQ];
__device__ __align__(128) __nv_bfloat16 g_ahi[(size_t)BATCH * SEQ * SEQ];
__device__ __align__(128) __nv_bfloat16 g_alo[(size_t)BATCH * SEQ * SEQ];
__device__ __align__(128) float         g_tvec[DIM];      // t = Wk^T bq
__device__ __align__(128) float         g_cst[1];         // bq . bk
__device__ __align__(128) float         g_vrow[NROWS];    // v_j (pre-scaled 1/32)
__device__ __align__(128) float         g_zero[DIM];      // zero bias (never written)

// ---------------------------------------------------------------------------
// PTX helpers (baseline PTX only — NO tcgen05: harness ptxas targets sm_103)
// ---------------------------------------------------------------------------
__device__ __forceinline__ uint32_t smem_u32(const void* p) {
    uint32_t a;
    asm("{ .reg .u64 t; cvta.to.shared.u64 t, %1; cvt.u32.u64 %0, t; }"
        : "=r"(a) : "l"(p));
    return a;
}

__device__ __forceinline__ void ldmatrix_x4(uint32_t& r0, uint32_t& r1,
                                            uint32_t& r2, uint32_t& r3,
                                            uint32_t addr) {
    asm volatile("ldmatrix.sync.aligned.m8n8.x4.shared.b16 {%0,%1,%2,%3}, [%4];"
                 : "=r"(r0), "=r"(r1), "=r"(r2), "=r"(r3) : "r"(addr));
}

__device__ __forceinline__ void mma_bf16(float* d, const uint32_t* a,
                                         const uint32_t* b) {
    asm volatile(
        "mma.sync.aligned.m16n8k16.row.col.f32.bf16.bf16.f32 "
        "{%0,%1,%2,%3}, {%4,%5,%6,%7}, {%8,%9}, {%0,%1,%2,%3};"
        : "+f"(d[0]), "+f"(d[1]), "+f"(d[2]), "+f"(d[3])
        : "r"(a[0]), "r"(a[1]), "r"(a[2]), "r"(a[3]),
          "r"(b[0]), "r"(b[1]));
}

#define CP_ASYNC16(smem, gptr) \
    asm volatile("cp.async.cg.shared.global [%0], [%1], 16;" \
                 :: "r"(smem), "l"(gptr) : "memory")
#define CP_COMMIT() asm volatile("cp.async.commit_group;" ::: "memory")
#define CP_WAIT(n)  asm volatile("cp.async.wait_group %0;" :: "n"(n) : "memory")

__device__ __forceinline__ void split2_store(__nv_bfloat16* hi, __nv_bfloat16* lo,
                                             long idx, float v0, float v1)
{
    __nv_bfloat16 h0 = __float2bfloat16(v0);
    __nv_bfloat16 h1 = __float2bfloat16(v1);
    *(__nv_bfloat162*)(hi + idx) = __halves2bfloat162(h0, h1);
    *(__nv_bfloat162*)(lo + idx) = __halves2bfloat162(
        __float2bfloat16(v0 - __bfloat162float(h0)),
        __float2bfloat16(v1 - __bfloat162float(h1)));
}

// ---------------------------------------------------------------------------
// Fused-segment bf16x3 GEMM via mma.sync + cp.async 3-stage pipeline, BK=64.
//   C[m,n] = alpha * sum_k A[m,k]*B[n,k] (+ bias), A ~ Ahi+Alo, B ~ Bhi+Blo.
//   Per K-tile, loads ALL FOUR tiles (Ahi, Alo, Bhi, Blo) into smem once and
//   issues the 3 products hh, hl, lh from resident data into one accumulator:
//   1.5x less L2 traffic and 1.5x fewer smem frag reads than 3-pass version,
//   3x fewer mainloop barriers.
//   Tile 128x128, BK=64, 256 thr = 8 warps (2m x 4n), warp tile 64x32.
//   smem rows padded to 72 elems (144B = 9*16B): aligned + conflict-free.
//   smem = 3 stages x 4 tiles x 18432 B = 221184 B -> 1 CTA/SM, 8 warps.
// EPI: 0 = fp32 out (alpha, no bias)
//      1 = bf16 hi/lo split out, column bias
//      2 = bf16 hi/lo split out, row bias
// ---------------------------------------------------------------------------
#define PAD    72
#define SMB    (128 * PAD * 2)          // 18432 bytes per tile
#define STAGEB (4 * SMB)                // 73728 bytes per stage (Ahi,Alo,Bhi,Blo)
#define NSTAGE 3
#define SMEM_TOTAL (NSTAGE * STAGEB)    // 221184

template <int EPI>
__global__ void __launch_bounds__(256, 1)
gemm_bf16x3(const __nv_bfloat16* __restrict__ Ahi, const __nv_bfloat16* __restrict__ Alo,
            const __nv_bfloat16* __restrict__ Bhi, const __nv_bfloat16* __restrict__ Blo,
            const float* __restrict__ bias,
            float* __restrict__ Cf,
            __nv_bfloat16* __restrict__ Chi, __nv_bfloat16* __restrict__ Clo,
            int K, int lda, int ldb, int ldc,
            long sA, long sB, long sC, float alpha)
{
    extern __shared__ __align__(128) char dsm[];
    const uint32_t smem_base = smem_u32(dsm);

    const int tid  = threadIdx.x;
    const int lane = tid & 31;
    const int wid  = tid >> 5;
    const int wm   = (wid >> 2) * 64;   // warp m origin (0 or 64)
    const int wn   = (wid & 3) * 32;    // warp n origin (0,32,64,96)

    const long m0 = (long)blockIdx.x * 128;
    const long n0 = (long)blockIdx.y * 128;
    const int  z  = blockIdx.z;
    const int  NT = K >> 6;             // 64-wide K tiles (segments fused!)

    const __nv_bfloat16* Ah = Ahi + (long)z * sA;
    const __nv_bfloat16* Al = Alo + (long)z * sA;
    const __nv_bfloat16* Bh = Bhi + (long)z * sB;
    const __nv_bfloat16* Bl = Blo + (long)z * sB;

    float acc[4][4][4];
    #pragma unroll
    for (int i = 0; i < 4; i++)
        #pragma unroll
        for (int j = 0; j < 4; j++)
            #pragma unroll
            for (int r = 0; r < 4; r++) acc[i][j][r] = 0.0f;

    auto issue_tile = [&](int t, int buf) {
        const long kk = (long)t << 6;
        const uint32_t st = smem_base + buf * STAGEB;
        #pragma unroll
        for (int i = 0; i < 4; i++) {
            const int c   = tid + i * 256;     // 0..1023
            const int row = c >> 3;            // 0..127
            const int j   = c & 7;             // 16B chunk within 64 k
            const uint32_t so = (uint32_t)(row * PAD + j * 8) * 2;
            const long ao = (m0 + row) * (long)lda + kk + j * 8;
            const long bo = (n0 + row) * (long)ldb + kk + j * 8;
            CP_ASYNC16(st + so,           Ah + ao);
            CP_ASYNC16(st + SMB + so,     Al + ao);
            CP_ASYNC16(st + 2 * SMB + so, Bh + bo);
            CP_ASYNC16(st + 3 * SMB + so, Bl + bo);
        }
        CP_COMMIT();
    };

    auto compute = [&](int buf) {
        const uint32_t st = smem_base + buf * STAGEB;
        const uint32_t abh = st;
        const uint32_t abl = st + SMB;
        const uint32_t bbh = st + 2 * SMB;
        const uint32_t bbl = st + 3 * SMB;
        #pragma unroll
        for (int ks = 0; ks < 4; ks++) {
            uint32_t ah[4][4], al[4][4], bh[4][2], bl[4][2];
            #pragma unroll
            for (int mt = 0; mt < 4; mt++) {
                const int row  = wm + mt * 16 + (lane & 15);
                const int koff = ks * 16 + ((lane >> 4) << 3);
                const uint32_t off = (uint32_t)(row * PAD + koff) * 2;
                ldmatrix_x4(ah[mt][0], ah[mt][1], ah[mt][2], ah[mt][3], abh + off);
                ldmatrix_x4(al[mt][0], al[mt][1], al[mt][2], al[mt][3], abl + off);
            }
            #pragma unroll
            for (int h = 0; h < 2; h++) {
                const int row  = wn + h * 16 + (lane & 7) + ((lane >> 4) << 3);
                const int koff = ks * 16 + ((lane >> 3) & 1) * 8;
                const uint32_t off = (uint32_t)(row * PAD + koff) * 2;
                ldmatrix_x4(bh[h * 2][0], bh[h * 2][1],
                            bh[h * 2 + 1][0], bh[h * 2 + 1][1], bbh + off);
                ldmatrix_x4(bl[h * 2][0], bl[h * 2][1],
                            bl[h * 2 + 1][0], bl[h * 2 + 1][1], bbl + off);
            }
            // 3 fused segment-products into one accumulator
            #pragma unroll
            for (int mt = 0; mt < 4; mt++)
                #pragma unroll
                for (int nt = 0; nt < 4; nt++) {
                    mma_bf16(acc[mt][nt], ah[mt], bh[nt]);   // hi*hi
                    mma_bf16(acc[mt][nt], ah[mt], bl[nt]);   // hi*lo
                    mma_bf16(acc[mt][nt], al[mt], bh[nt]);   // lo*hi
                }
        }
    };

    // 3-stage pipeline, one barrier per BK=64 iteration.
    issue_tile(0, 0);
    issue_tile(1, 1);
    for (int t = 0; t < NT; t++) {
        CP_WAIT(1);                 // group t complete
        __syncthreads();
        if (t + 2 < NT) issue_tile(t + 2, (t + 2) % 3);   // overwrites buf read at t-1
        compute(t % 3);
    }

    // epilogue
    const int g   = lane >> 2;
    const int tg2 = (lane & 3) * 2;
    #pragma unroll
    for (int mt = 0; mt < 4; mt++) {
        #pragma unroll
        for (int half = 0; half < 2; half++) {
            const long row = m0 + wm + mt * 16 + g + half * 8;
            const long rbase = (long)z * sC + row * (long)ldc;
            #pragma unroll
            for (int nt = 0; nt < 4; nt++) {
                const long col = n0 + wn + nt * 8 + tg2;
                float v0 = acc[mt][nt][half * 2 + 0] * alpha;
                float v1 = acc[mt][nt][half * 2 + 1] * alpha;
                if (EPI == 0) {
                    *(float2*)(Cf + rbase + col) = make_float2(v0, v1);
                } else if (EPI == 1) {
                    v0 += bias[col];
                    v1 += bias[col + 1];
                    split2_store(Chi, Clo, rbase + col, v0, v1);
                } else {
                    const float b = bias[row];
                    split2_store(Chi, Clo, rbase + col, v0 + b, v1 + b);
                }
            }
        }
    }
}

// ---------------------------------------------------------------------------
// fp32 -> bf16 hi/lo split
// ---------------------------------------------------------------------------
__device__ __forceinline__ void split_store4(__nv_bfloat16* hi, __nv_bfloat16* lo,
                                             long idx, float4 v)
{
    split2_store(hi, lo, idx,     v.x, v.y);
    split2_store(hi, lo, idx + 2, v.z, v.w);
}

__global__ void __launch_bounds__(256)
split_kernel(const float* __restrict__ in, __nv_bfloat16* __restrict__ hi,
             __nv_bfloat16* __restrict__ lo, long n)
{
    long i = ((long)blockIdx.x * 256 + threadIdx.x) * 4;
    if (i >= n) return;
    float4 f = *(const float4*)(in + i);
    split_store4(hi, lo, i, f);
}

// Generic transpose + split: in [R, C] fp32 -> out [C, R] bf16 hi/lo
__global__ void __launch_bounds__(256)
transpose_split_kernel(const float* __restrict__ in,
                       __nv_bfloat16* __restrict__ oh,
                       __nv_bfloat16* __restrict__ ol, int R, int C)
{
    __shared__ float t[32][33];
    const int r0 = blockIdx.y * 32;
    const int c0 = blockIdx.x * 32;
    const int tx = threadIdx.x, ty = threadIdx.y;

    #pragma unroll
    for (int j = 0; j < 4; j++)
        t[ty + 8 * j][tx] = in[(long)(r0 + ty + 8 * j) * C + c0 + tx];
    __syncthreads();
    #pragma unroll
    for (int j = 0; j < 4; j++) {
        float val = t[tx][ty + 8 * j];
        long o = (long)(c0 + ty + 8 * j) * R + r0 + tx;
        __nv_bfloat16 h = __float2bfloat16(val);
        oh[o] = h;
        ol[o] = __float2bfloat16(val - __bfloat162float(h));
    }
}

// ---------------------------------------------------------------------------
// t = Wk^T bq (t_d = sum_e bq[e] * Wk[e,d]); also c = bq . bk (block 0)
// ---------------------------------------------------------------------------
__global__ void __launch_bounds__(256)
t_kernel(const float* __restrict__ Wk, const float* __restrict__ bq,
         const float* __restrict__ bk, float* __restrict__ t,
         float* __restrict__ cst)
{
    const int d = blockIdx.x * 256 + threadIdx.x;
    float a0 = 0.f, a1 = 0.f, a2 = 0.f, a3 = 0.f;
    for (int e = 0; e < DIM; e += 4) {
        a0 += bq[e]     * Wk[(long)e * DIM + d];
        a1 += bq[e + 1] * Wk[(long)(e + 1) * DIM + d];
        a2 += bq[e + 2] * Wk[(long)(e + 2) * DIM + d];
        a3 += bq[e + 3] * Wk[(long)(e + 3) * DIM + d];
    }
    t[d] = (a0 + a1) + (a2 + a3);

    if (blockIdx.x == 0) {
        float c = 0.f;
        for (int e = threadIdx.x; e < DIM; e += 256) c += bq[e] * bk[e];
        __shared__ float red[8];
        const int lane = threadIdx.x & 31, wid = threadIdx.x >> 5;
        #pragma unroll
        for (int o = 16; o > 0; o >>= 1) c += __shfl_xor_sync(0xffffffffu, c, o);
        if (lane == 0) red[wid] = c;
        __syncthreads();
        if (threadIdx.x == 0) {
            float s = 0.f;
            #pragma unroll
            for (int w = 0; w < 8; w++) s += red[w];
            cst[0] = s;
        }
    }
}

// ---------------------------------------------------------------------------
// v_j = (x_j . t + c) / 32      (one warp per row)
// ---------------------------------------------------------------------------
__global__ void __launch_bounds__(256)
v_kernel(const float* __restrict__ x, const float* __restrict__ t,
         const float* __restrict__ cst, float* __restrict__ v)
{
    const int wid = threadIdx.x >> 5, lane = threadIdx.x & 31;
    const long j = (long)blockIdx.x * 8 + wid;
    const float4* xr = (const float4*)(x + j * DIM);
    const float4* tr = (const float4*)t;
    float acc = 0.f;
    #pragma unroll
    for (int i = 0; i < 8; i++) {
        float4 a = xr[lane + 32 * i];
        float4 b = tr[lane + 32 * i];
        acc += a.x * b.x + a.y * b.y + a.z * b.z + a.w * b.w;
    }
    #pragma unroll
    for (int o = 16; o > 0; o >>= 1) acc += __shfl_xor_sync(0xffffffffu, acc, o);
    if (lane == 0) v[j] = (acc + cst[0]) * (1.0f / 32.0f);
}

// ---------------------------------------------------------------------------
// Row softmax of (S + v[col]) fused with hi/lo split of probabilities.
// ---------------------------------------------------------------------------
__global__ void __launch_bounds__(256)
softmax_split_kernel(const float* __restrict__ S, const float* __restrict__ Vv,
                     __nv_bfloat16* __restrict__ Ahi,
                     __nv_bfloat16* __restrict__ Alo)
{
    __shared__ float red[8];
    __shared__ float bcast;

    const long row = blockIdx.x;
    const float4* p4 = (const float4*)(S + row * (long)SEQ);
    const float4* vp = (const float4*)(Vv + (row & ~(long)(SEQ - 1)));
    const int tid  = threadIdx.x;
    const int lane = tid & 31;
    const int wid  = tid >> 5;

    float4 v0 = p4[tid];
    float4 v1 = p4[tid + 256];
    float4 a0 = vp[tid];
    float4 a1 = vp[tid + 256];
    v0.x += a0.x; v0.y += a0.y; v0.z += a0.z; v0.w += a0.w;
    v1.x += a1.x; v1.y += a1.y; v1.z += a1.z; v1.w += a1.w;

    float m = fmaxf(fmaxf(fmaxf(v0.x, v0.y), fmaxf(v0.z, v0.w)),
                    fmaxf(fmaxf(v1.x, v1.y), fmaxf(v1.z, v1.w)));
    #pragma unroll
    for (int o = 16; o > 0; o >>= 1) m = fmaxf(m, __shfl_xor_sync(0xffffffffu, m, o));
    if (lane == 0) red[wid] = m;
    __syncthreads();
    if (wid == 0) {
        float x = (lane < 8) ? red[lane] : -3.4e38f;
        #pragma unroll
        for (int o = 4; o > 0; o >>= 1) x = fmaxf(x, __shfl_xor_sync(0xffffffffu, x, o));
        if (lane == 0) bcast = x;
    }
    __syncthreads();
    m = bcast;
    __syncthreads();

    v0.x = __expf(v0.x - m); v0.y = __expf(v0.y - m);
    v0.z = __expf(v0.z - m); v0.w = __expf(v0.w - m);
    v1.x = __expf(v1.x - m); v1.y = __expf(v1.y - m);
    v1.z = __expf(v1.z - m); v1.w = __expf(v1.w - m);
    float s = (v0.x + v0.y + v0.z + v0.w) + (v1.x + v1.y + v1.z + v1.w);
    #pragma unroll
    for (int o = 16; o > 0; o >>= 1) s += __shfl_xor_sync(0xffffffffu, s, o);
    if (lane == 0) red[wid] = s;
    __syncthreads();
    if (wid == 0) {
        float x = (lane < 8) ? red[lane] : 0.0f;
        #pragma unroll
        for (int o = 4; o > 0; o >>= 1) x += __shfl_xor_sync(0xffffffffu, x, o);
        if (lane == 0) bcast = x;
    }
    __syncthreads();
    const float inv = 1.0f / bcast;

    v0.x *= inv; v0.y *= inv; v0.z *= inv; v0.w *= inv;
    v1.x *= inv; v1.y *= inv; v1.z *= inv; v1.w *= inv;

    const long base = row * (long)SEQ;
    split_store4(Ahi, Alo, base + tid * 4, v0);
    split_store4(Ahi, Alo, base + 1024 + tid * 4, v1);
}

// ---------------------------------------------------------------------------
// kernel_launch
// inputs: x, Wq, bq, Wk, bk, Wv, bv
//
// Algebra: softmax is row-shift invariant, so
//   scores = (x Wq^T + bq)(x Wk^T + bk)^T / 32
//          ~ x (Wq^T Wk) x^T / 32 + 1 v^T   (row-constant terms dropped)
//   with v_j = (x_j . (Wk^T bq) + bq.bk)/32.
// out = attn . (x Wv^T + bv).
// ---------------------------------------------------------------------------
extern "C" void kernel_launch(void* const* d_in, const int* in_sizes, int n_in,
                              void* d_out, int out_size)
{
    const float* x  = (const float*)d_in[0];
    const float* Wq = (const float*)d_in[1];
    const float* bq = (const float*)d_in[2];
    const float* Wk = (const float*)d_in[3];
    const float* bk = (const float*)d_in[4];
    const float* Wv = (const float*)d_in[5];
    const float* bv = (const float*)d_in[6];
    float* out = (float*)d_out;

    __nv_bfloat16 *xhi, *xlo, *wvhi, *wvlo, *wqthi, *wqtlo, *wkthi, *wktlo;
    __nv_bfloat16 *mthi, *mtlo, *phi, *plo, *vthi, *vtlo, *ahi, *alo;
    float *sc, *tvec, *cst, *vrow, *zero;
    cudaGetSymbolAddress((void**)&xhi,   g_xhi);
    cudaGetSymbolAddress((void**)&xlo,   g_xlo);
    cudaGetSymbolAddress((void**)&wvhi,  g_wvhi);
    cudaGetSymbolAddress((void**)&wvlo,  g_wvlo);
    cudaGetSymbolAddress((void**)&wqthi, g_wqthi);
    cudaGetSymbolAddress((void**)&wqtlo, g_wqtlo);
    cudaGetSymbolAddress((void**)&wkthi, g_wkthi);
    cudaGetSymbolAddress((void**)&wktlo, g_wktlo);
    cudaGetSymbolAddress((void**)&mthi,  g_mthi);
    cudaGetSymbolAddress((void**)&mtlo,  g_mtlo);
    cudaGetSymbolAddress((void**)&phi,   g_phi);
    cudaGetSymbolAddress((void**)&plo,   g_plo);
    cudaGetSymbolAddress((void**)&vthi,  g_vthi);
    cudaGetSymbolAddress((void**)&vtlo,  g_vtlo);
    cudaGetSymbolAddress((void**)&sc,    g_s);
    cudaGetSymbolAddress((void**)&ahi,   g_ahi);
    cudaGetSymbolAddress((void**)&alo,   g_alo);
    cudaGetSymbolAddress((void**)&tvec,  g_tvec);
    cudaGetSymbolAddress((void**)&cst,   g_cst);
    cudaGetSymbolAddress((void**)&vrow,  g_vrow);
    cudaGetSymbolAddress((void**)&zero,  g_zero);

    cudaFuncSetAttribute(gemm_bf16x3<0>, cudaFuncAttributeMaxDynamicSharedMemorySize, SMEM_TOTAL);
    cudaFuncSetAttribute(gemm_bf16x3<1>, cudaFuncAttributeMaxDynamicSharedMemorySize, SMEM_TOTAL);
    cudaFuncSetAttribute(gemm_bf16x3<2>, cudaFuncAttributeMaxDynamicSharedMemorySize, SMEM_TOTAL);

    const long nxd = (long)NROWS * DIM;
    const long nww = (long)DIM * DIM;

    // pre-passes
    split_kernel<<<(int)(nxd / 4 / 256), 256>>>(x,  xhi,  xlo,  nxd);
    split_kernel<<<(int)(nww / 4 / 256), 256>>>(Wv, wvhi, wvlo, nww);
    {
        dim3 grid(DIM / 32, DIM / 32);
        dim3 blk(32, 8);
        transpose_split_kernel<<<grid, blk>>>(Wq, wqthi, wqtlo, DIM, DIM);
        transpose_split_kernel<<<grid, blk>>>(Wk, wkthi, wktlo, DIM, DIM);
    }
    t_kernel<<<DIM / 256, 256>>>(Wk, bq, bk, tvec, cst);
    v_kernel<<<NROWS / 8, 256>>>(x, tvec, cst, vrow);

    // Mt[d',d] = sum_e Wk[e,d'] Wq[e,d] -> split out
    {
        dim3 grid(DIM / 128, DIM / 128, 1);
        gemm_bf16x3<1><<<grid, 256, SMEM_TOTAL>>>(wkthi, wktlo, wqthi, wqtlo, zero,
                                                  nullptr, mthi, mtlo,
                                                  DIM, DIM, DIM, DIM, 0, 0, 0, 1.0f);
    }
    // P[s,d'] = sum_d x[s,d] Mt[d',d] -> split out
    {
        dim3 grid(NROWS / 128, DIM / 128, 1);
        gemm_bf16x3<1><<<grid, 256, SMEM_TOTAL>>>(xhi, xlo, mthi, mtlo, zero,
                                                  nullptr, phi, plo,
                                                  DIM, DIM, DIM, DIM, 0, 0, 0, 1.0f);
    }
    // Vt[d,s] = sum_k Wv[d,k] x[s,k] + bv[d] (row bias) -> split out, [D, B*S]
    {
        dim3 grid(DIM / 128, NROWS / 128, 1);
        gemm_bf16x3<2><<<grid, 256, SMEM_TOTAL>>>(wvhi, wvlo, xhi, xlo, bv,
                                                  nullptr, vthi, vtlo,
                                                  DIM, DIM, DIM, NROWS, 0, 0, 0, 1.0f);
    }
    // scores: per batch  P[2048,1024] x x[2048,1024]^T * 1/32 -> fp32
    {
        dim3 grid(SEQ / 128, SEQ / 128, BATCH);
        gemm_bf16x3<0><<<grid, 256, SMEM_TOTAL>>>(phi, plo, xhi, xlo, nullptr,
                                                  sc, nullptr, nullptr,
                                                  DIM, DIM, DIM, SEQ,
                                                  (long)SEQ * DIM, (long)SEQ * DIM,
                                                  (long)SEQ * SEQ, 1.0f / 32.0f);
    }
    // softmax(scores + v[col]) + split attn
    softmax_split_kernel<<<NROWS, 256>>>(sc, vrow, ahi, alo);

    // out: per batch attn[2048,2048] x Vt[:, b*2048 : (b+1)*2048]^T -> fp32
    {
        dim3 grid(SEQ / 128, DIM / 128, BATCH);
        gemm_bf16x3<0><<<grid, 256, SMEM_TOTAL>>>(ahi, alo, vthi, vtlo, nullptr,
                                                  out, nullptr, nullptr,
                                                  SEQ, SEQ, NROWS, DIM,
                                                  (long)SEQ * SEQ, (long)SEQ,
                                                  (long)SEQ * DIM, 1.0f);
    }
}

// round 17
// speedup vs baseline: 1.2056x; 1.0143x over previous
#include <cuda_runtime.h>
#include <cuda_bf16.h>
#include <stdint.h>
#include <math.h>

// ---------------------------------------------------------------------------
// Problem constants
// ---------------------------------------------------------------------------
#define BATCH 4
#define SEQ   2048
#define DIM   1024
#define NROWS (BATCH * SEQ)          // 8192

// ---------------------------------------------------------------------------
// Scratch (device globals: allocation-free; zero-initialized by CUDA)
// ---------------------------------------------------------------------------
__device__ __align__(128) __nv_bfloat16 g_xhi[(size_t)NROWS * DIM];
__device__ __align__(128) __nv_bfloat16 g_xlo[(size_t)NROWS * DIM];
__device__ __align__(128) __nv_bfloat16 g_wvhi[(size_t)DIM * DIM];
__device__ __align__(128) __nv_bfloat16 g_wvlo[(size_t)DIM * DIM];
__device__ __align__(128) __nv_bfloat16 g_wqthi[(size_t)DIM * DIM];  // Wq^T split
__device__ __align__(128) __nv_bfloat16 g_wqtlo[(size_t)DIM * DIM];
__device__ __align__(128) __nv_bfloat16 g_wkthi[(size_t)DIM * DIM];  // Wk^T split
__device__ __align__(128) __nv_bfloat16 g_wktlo[(size_t)DIM * DIM];
__device__ __align__(128) __nv_bfloat16 g_mthi[(size_t)DIM * DIM];   // Mt = (Wq^T Wk)^T
__device__ __align__(128) __nv_bfloat16 g_mtlo[(size_t)DIM * DIM];
__device__ __align__(128) __nv_bfloat16 g_phi[(size_t)NROWS * DIM];  // P = x M
__device__ __align__(128) __nv_bfloat16 g_plo[(size_t)NROWS * DIM];
__device__ __align__(128) __nv_bfloat16 g_vthi[(size_t)DIM * NROWS]; // Vt [D, B*S]
__device__ __align__(128) __nv_bfloat16 g_vtlo[(size_t)DIM * NROWS];
__device__ __align__(128) float         g_s[(size_t)BATCH * SEQ * SEQ];
__device__ __align__(128) __nv_bfloat16 g_ahi[(size_t)BATCH * SEQ * SEQ];
__device__ __align__(128) __nv_bfloat16 g_alo[(size_t)BATCH * SEQ * SEQ];
__device__ __align__(128) float         g_tvec[DIM];      // t = Wk^T bq
__device__ __align__(128) float         g_cst[1];         // bq . bk
__device__ __align__(128) float         g_vrow[NROWS];    // v_j (pre-scaled 1/32)
__device__ __align__(128) float         g_zero[DIM];      // zero bias (never written)

// ---------------------------------------------------------------------------
// PTX helpers (baseline PTX only — NO tcgen05: harness ptxas targets sm_103)
// ---------------------------------------------------------------------------
__device__ __forceinline__ uint32_t smem_u32(const void* p) {
    uint32_t a;
    asm("{ .reg .u64 t; cvta.to.shared.u64 t, %1; cvt.u32.u64 %0, t; }"
        : "=r"(a) : "l"(p));
    return a;
}

__device__ __forceinline__ void ldmatrix_x4(uint32_t& r0, uint32_t& r1,
                                            uint32_t& r2, uint32_t& r3,
                                            uint32_t addr) {
    asm volatile("ldmatrix.sync.aligned.m8n8.x4.shared.b16 {%0,%1,%2,%3}, [%4];"
                 : "=r"(r0), "=r"(r1), "=r"(r2), "=r"(r3) : "r"(addr));
}

__device__ __forceinline__ void mma_bf16(float* d, const uint32_t* a,
                                         const uint32_t* b) {
    asm volatile(
        "mma.sync.aligned.m16n8k16.row.col.f32.bf16.bf16.f32 "
        "{%0,%1,%2,%3}, {%4,%5,%6,%7}, {%8,%9}, {%0,%1,%2,%3};"
        : "+f"(d[0]), "+f"(d[1]), "+f"(d[2]), "+f"(d[3])
        : "r"(a[0]), "r"(a[1]), "r"(a[2]), "r"(a[3]),
          "r"(b[0]), "r"(b[1]));
}

#define CP_ASYNC16(smem, gptr) \
    asm volatile("cp.async.cg.shared.global [%0], [%1], 16;" \
                 :: "r"(smem), "l"(gptr) : "memory")
#define CP_COMMIT() asm volatile("cp.async.commit_group;" ::: "memory")
#define CP_WAIT(n)  asm volatile("cp.async.wait_group %0;" :: "n"(n) : "memory")

__device__ __forceinline__ void split2_store(__nv_bfloat16* hi, __nv_bfloat16* lo,
                                             long idx, float v0, float v1)
{
    __nv_bfloat16 h0 = __float2bfloat16(v0);
    __nv_bfloat16 h1 = __float2bfloat16(v1);
    *(__nv_bfloat162*)(hi + idx) = __halves2bfloat162(h0, h1);
    *(__nv_bfloat162*)(lo + idx) = __halves2bfloat162(
        __float2bfloat16(v0 - __bfloat162float(h0)),
        __float2bfloat16(v1 - __bfloat162float(h1)));
}

// ---------------------------------------------------------------------------
// Fused-segment bf16x3 GEMM via mma.sync + cp.async, BK=32, 2-stage, 2 CTA/SM.
//   C[m,n] = alpha * sum_k A[m,k]*B[n,k] (+ bias), A ~ Ahi+Alo, B ~ Bhi+Blo.
//   Per K-tile, all four tiles (Ahi, Alo, Bhi, Blo) resident in smem; the 3
//   products hh, hl, lh accumulate into one fp32 accumulator.
//   Tile 128x128, BK=32, 256 thr = 8 warps (2m x 4n), warp tile 64x32.
//   smem rows padded to 40 elems (80B = 5*16B): aligned + conflict-free.
//   smem = 2 stages x 4 tiles x 10240 B = 81920 B -> 2 CTAs/SM (occupancy
//   overlap hides barrier/wait/epilogue bubbles that bound round 15).
//   2-stage/1-barrier pipeline: [wait(0); sync; issue(t+1); compute(t)]
//   - wait(0): group t (issued 1 full iteration ago; L2-resident operands)
//   - sync: publishes group-t smem AND fences buffer (t+1)&1 (read by
//     compute(t-1), finished before this sync) against the issue below.
// EPI: 0 = fp32 out; 1 = split out + col bias; 2 = split out + row bias
// ---------------------------------------------------------------------------
#define PAD    40
#define SMB    (128 * PAD * 2)          // 10240 bytes per tile
#define STAGEB (4 * SMB)                // 40960 bytes per stage
#define NSTAGE 2
#define SMEM_TOTAL (NSTAGE * STAGEB)    // 81920

template <int EPI>
__global__ void __launch_bounds__(256, 2)
gemm_bf16x3(const __nv_bfloat16* __restrict__ Ahi, const __nv_bfloat16* __restrict__ Alo,
            const __nv_bfloat16* __restrict__ Bhi, const __nv_bfloat16* __restrict__ Blo,
            const float* __restrict__ bias,
            float* __restrict__ Cf,
            __nv_bfloat16* __restrict__ Chi, __nv_bfloat16* __restrict__ Clo,
            int K, int lda, int ldb, int ldc,
            long sA, long sB, long sC, float alpha)
{
    extern __shared__ __align__(128) char dsm[];
    const uint32_t smem_base = smem_u32(dsm);

    const int tid  = threadIdx.x;
    const int lane = tid & 31;
    const int wid  = tid >> 5;
    const int wm   = (wid >> 2) * 64;   // warp m origin (0 or 64)
    const int wn   = (wid & 3) * 32;    // warp n origin (0,32,64,96)

    const long m0 = (long)blockIdx.x * 128;
    const long n0 = (long)blockIdx.y * 128;
    const int  z  = blockIdx.z;
    const int  NT = K >> 5;             // 32-wide K tiles (segments fused)

    const __nv_bfloat16* Ah = Ahi + (long)z * sA;
    const __nv_bfloat16* Al = Alo + (long)z * sA;
    const __nv_bfloat16* Bh = Bhi + (long)z * sB;
    const __nv_bfloat16* Bl = Blo + (long)z * sB;

    float acc[4][4][4];
    #pragma unroll
    for (int i = 0; i < 4; i++)
        #pragma unroll
        for (int j = 0; j < 4; j++)
            #pragma unroll
            for (int r = 0; r < 4; r++) acc[i][j][r] = 0.0f;

    auto issue_tile = [&](int t, int buf) {
        const long kk = (long)t << 5;
        const uint32_t st = smem_base + buf * STAGEB;
        #pragma unroll
        for (int i = 0; i < 2; i++) {
            const int c   = tid + i * 256;     // 0..511
            const int row = c >> 2;            // 0..127
            const int j   = c & 3;             // 16B chunk within 32 k
            const uint32_t so = (uint32_t)(row * PAD + j * 8) * 2;
            const long ao = (m0 + row) * (long)lda + kk + j * 8;
            const long bo = (n0 + row) * (long)ldb + kk + j * 8;
            CP_ASYNC16(st + so,           Ah + ao);
            CP_ASYNC16(st + SMB + so,     Al + ao);
            CP_ASYNC16(st + 2 * SMB + so, Bh + bo);
            CP_ASYNC16(st + 3 * SMB + so, Bl + bo);
        }
        CP_COMMIT();
    };

    auto compute = [&](int buf) {
        const uint32_t st = smem_base + buf * STAGEB;
        #pragma unroll
        for (int ks = 0; ks < 2; ks++) {
            // B fragments first (16 regs live), then A per-mt (8 regs live)
            uint32_t bh[4][2], bl[4][2];
            #pragma unroll
            for (int h = 0; h < 2; h++) {
                const int row  = wn + h * 16 + (lane & 7) + ((lane >> 4) << 3);
                const int koff = ks * 16 + ((lane >> 3) & 1) * 8;
                const uint32_t off = (uint32_t)(row * PAD + koff) * 2;
                ldmatrix_x4(bh[h * 2][0], bh[h * 2][1],
                            bh[h * 2 + 1][0], bh[h * 2 + 1][1], st + 2 * SMB + off);
                ldmatrix_x4(bl[h * 2][0], bl[h * 2][1],
                            bl[h * 2 + 1][0], bl[h * 2 + 1][1], st + 3 * SMB + off);
            }
            #pragma unroll
            for (int mt = 0; mt < 4; mt++) {
                uint32_t ah[4], al[4];
                const int row  = wm + mt * 16 + (lane & 15);
                const int koff = ks * 16 + ((lane >> 4) << 3);
                const uint32_t off = (uint32_t)(row * PAD + koff) * 2;
                ldmatrix_x4(ah[0], ah[1], ah[2], ah[3], st + off);
                ldmatrix_x4(al[0], al[1], al[2], al[3], st + SMB + off);
                #pragma unroll
                for (int nt = 0; nt < 4; nt++) {
                    mma_bf16(acc[mt][nt], ah, bh[nt]);   // hi*hi
                    mma_bf16(acc[mt][nt], ah, bl[nt]);   // hi*lo
                    mma_bf16(acc[mt][nt], al, bh[nt]);   // lo*hi
                }
            }
        }
    };

    // 2-stage pipeline, one barrier per BK=32 iteration.
    issue_tile(0, 0);
    for (int t = 0; t < NT; t++) {
        CP_WAIT(0);                 // group t landed (issued 1 iter ago)
        __syncthreads();            // publish group t; fence buf reuse
        if (t + 1 < NT) issue_tile(t + 1, (t + 1) & 1);
        compute(t & 1);
    }

    // epilogue
    const int g   = lane >> 2;
    const int tg2 = (lane & 3) * 2;
    #pragma unroll
    for (int mt = 0; mt < 4; mt++) {
        #pragma unroll
        for (int half = 0; half < 2; half++) {
            const long row = m0 + wm + mt * 16 + g + half * 8;
            const long rbase = (long)z * sC + row * (long)ldc;
            #pragma unroll
            for (int nt = 0; nt < 4; nt++) {
                const long col = n0 + wn + nt * 8 + tg2;
                float v0 = acc[mt][nt][half * 2 + 0] * alpha;
                float v1 = acc[mt][nt][half * 2 + 1] * alpha;
                if (EPI == 0) {
                    *(float2*)(Cf + rbase + col) = make_float2(v0, v1);
                } else if (EPI == 1) {
                    v0 += bias[col];
                    v1 += bias[col + 1];
                    split2_store(Chi, Clo, rbase + col, v0, v1);
                } else {
                    const float b = bias[row];
                    split2_store(Chi, Clo, rbase + col, v0 + b, v1 + b);
                }
            }
        }
    }
}

// ---------------------------------------------------------------------------
// fp32 -> bf16 hi/lo split
// ---------------------------------------------------------------------------
__device__ __forceinline__ void split_store4(__nv_bfloat16* hi, __nv_bfloat16* lo,
                                             long idx, float4 v)
{
    split2_store(hi, lo, idx,     v.x, v.y);
    split2_store(hi, lo, idx + 2, v.z, v.w);
}

__global__ void __launch_bounds__(256)
split_kernel(const float* __restrict__ in, __nv_bfloat16* __restrict__ hi,
             __nv_bfloat16* __restrict__ lo, long n)
{
    long i = ((long)blockIdx.x * 256 + threadIdx.x) * 4;
    if (i >= n) return;
    float4 f = *(const float4*)(in + i);
    split_store4(hi, lo, i, f);
}

// Generic transpose + split: in [R, C] fp32 -> out [C, R] bf16 hi/lo
__global__ void __launch_bounds__(256)
transpose_split_kernel(const float* __restrict__ in,
                       __nv_bfloat16* __restrict__ oh,
                       __nv_bfloat16* __restrict__ ol, int R, int C)
{
    __shared__ float t[32][33];
    const int r0 = blockIdx.y * 32;
    const int c0 = blockIdx.x * 32;
    const int tx = threadIdx.x, ty = threadIdx.y;

    #pragma unroll
    for (int j = 0; j < 4; j++)
        t[ty + 8 * j][tx] = in[(long)(r0 + ty + 8 * j) * C + c0 + tx];
    __syncthreads();
    #pragma unroll
    for (int j = 0; j < 4; j++) {
        float val = t[tx][ty + 8 * j];
        long o = (long)(c0 + ty + 8 * j) * R + r0 + tx;
        __nv_bfloat16 h = __float2bfloat16(val);
        oh[o] = h;
        ol[o] = __float2bfloat16(val - __bfloat162float(h));
    }
}

// ---------------------------------------------------------------------------
// t = Wk^T bq (t_d = sum_e bq[e] * Wk[e,d]); also c = bq . bk (block 0)
// ---------------------------------------------------------------------------
__global__ void __launch_bounds__(256)
t_kernel(const float* __restrict__ Wk, const float* __restrict__ bq,
         const float* __restrict__ bk, float* __restrict__ t,
         float* __restrict__ cst)
{
    const int d = blockIdx.x * 256 + threadIdx.x;
    float a0 = 0.f, a1 = 0.f, a2 = 0.f, a3 = 0.f;
    for (int e = 0; e < DIM; e += 4) {
        a0 += bq[e]     * Wk[(long)e * DIM + d];
        a1 += bq[e + 1] * Wk[(long)(e + 1) * DIM + d];
        a2 += bq[e + 2] * Wk[(long)(e + 2) * DIM + d];
        a3 += bq[e + 3] * Wk[(long)(e + 3) * DIM + d];
    }
    t[d] = (a0 + a1) + (a2 + a3);

    if (blockIdx.x == 0) {
        float c = 0.f;
        for (int e = threadIdx.x; e < DIM; e += 256) c += bq[e] * bk[e];
        __shared__ float red[8];
        const int lane = threadIdx.x & 31, wid = threadIdx.x >> 5;
        #pragma unroll
        for (int o = 16; o > 0; o >>= 1) c += __shfl_xor_sync(0xffffffffu, c, o);
        if (lane == 0) red[wid] = c;
        __syncthreads();
        if (threadIdx.x == 0) {
            float s = 0.f;
            #pragma unroll
            for (int w = 0; w < 8; w++) s += red[w];
            cst[0] = s;
        }
    }
}

// ---------------------------------------------------------------------------
// v_j = (x_j . t + c) / 32      (one warp per row)
// ---------------------------------------------------------------------------
__global__ void __launch_bounds__(256)
v_kernel(const float* __restrict__ x, const float* __restrict__ t,
         const float* __restrict__ cst, float* __restrict__ v)
{
    const int wid = threadIdx.x >> 5, lane = threadIdx.x & 31;
    const long j = (long)blockIdx.x * 8 + wid;
    const float4* xr = (const float4*)(x + j * DIM);
    const float4* tr = (const float4*)t;
    float acc = 0.f;
    #pragma unroll
    for (int i = 0; i < 8; i++) {
        float4 a = xr[lane + 32 * i];
        float4 b = tr[lane + 32 * i];
        acc += a.x * b.x + a.y * b.y + a.z * b.z + a.w * b.w;
    }
    #pragma unroll
    for (int o = 16; o > 0; o >>= 1) acc += __shfl_xor_sync(0xffffffffu, acc, o);
    if (lane == 0) v[j] = (acc + cst[0]) * (1.0f / 32.0f);
}

// ---------------------------------------------------------------------------
// Row softmax of (S + v[col]) fused with hi/lo split of probabilities.
// ---------------------------------------------------------------------------
__global__ void __launch_bounds__(256)
softmax_split_kernel(const float* __restrict__ S, const float* __restrict__ Vv,
                     __nv_bfloat16* __restrict__ Ahi,
                     __nv_bfloat16* __restrict__ Alo)
{
    __shared__ float red[8];
    __shared__ float bcast;

    const long row = blockIdx.x;
    const float4* p4 = (const float4*)(S + row * (long)SEQ);
    const float4* vp = (const float4*)(Vv + (row & ~(long)(SEQ - 1)));
    const int tid  = threadIdx.x;
    const int lane = tid & 31;
    const int wid  = tid >> 5;

    float4 v0 = p4[tid];
    float4 v1 = p4[tid + 256];
    float4 a0 = vp[tid];
    float4 a1 = vp[tid + 256];
    v0.x += a0.x; v0.y += a0.y; v0.z += a0.z; v0.w += a0.w;
    v1.x += a1.x; v1.y += a1.y; v1.z += a1.z; v1.w += a1.w;

    float m = fmaxf(fmaxf(fmaxf(v0.x, v0.y), fmaxf(v0.z, v0.w)),
                    fmaxf(fmaxf(v1.x, v1.y), fmaxf(v1.z, v1.w)));
    #pragma unroll
    for (int o = 16; o > 0; o >>= 1) m = fmaxf(m, __shfl_xor_sync(0xffffffffu, m, o));
    if (lane == 0) red[wid] = m;
    __syncthreads();
    if (wid == 0) {
        float x = (lane < 8) ? red[lane] : -3.4e38f;
        #pragma unroll
        for (int o = 4; o > 0; o >>= 1) x = fmaxf(x, __shfl_xor_sync(0xffffffffu, x, o));
        if (lane == 0) bcast = x;
    }
    __syncthreads();
    m = bcast;
    __syncthreads();

    v0.x = __expf(v0.x - m); v0.y = __expf(v0.y - m);
    v0.z = __expf(v0.z - m); v0.w = __expf(v0.w - m);
    v1.x = __expf(v1.x - m); v1.y = __expf(v1.y - m);
    v1.z = __expf(v1.z - m); v1.w = __expf(v1.w - m);
    float s = (v0.x + v0.y + v0.z + v0.w) + (v1.x + v1.y + v1.z + v1.w);
    #pragma unroll
    for (int o = 16; o > 0; o >>= 1) s += __shfl_xor_sync(0xffffffffu, s, o);
    if (lane == 0) red[wid] = s;
    __syncthreads();
    if (wid == 0) {
        float x = (lane < 8) ? red[lane] : 0.0f;
        #pragma unroll
        for (int o = 4; o > 0; o >>= 1) x += __shfl_xor_sync(0xffffffffu, x, o);
        if (lane == 0) bcast = x;
    }
    __syncthreads();
    const float inv = 1.0f / bcast;

    v0.x *= inv; v0.y *= inv; v0.z *= inv; v0.w *= inv;
    v1.x *= inv; v1.y *= inv; v1.z *= inv; v1.w *= inv;

    const long base = row * (long)SEQ;
    split_store4(Ahi, Alo, base + tid * 4, v0);
    split_store4(Ahi, Alo, base + 1024 + tid * 4, v1);
}

// ---------------------------------------------------------------------------
// kernel_launch
// inputs: x, Wq, bq, Wk, bk, Wv, bv
//
// Algebra: softmax is row-shift invariant, so
//   scores = (x Wq^T + bq)(x Wk^T + bk)^T / 32
//          ~ x (Wq^T Wk) x^T / 32 + 1 v^T   (row-constant terms dropped)
//   with v_j = (x_j . (Wk^T bq) + bq.bk)/32.
// out = attn . (x Wv^T + bv).
// ---------------------------------------------------------------------------
extern "C" void kernel_launch(void* const* d_in, const int* in_sizes, int n_in,
                              void* d_out, int out_size)
{
    const float* x  = (const float*)d_in[0];
    const float* Wq = (const float*)d_in[1];
    const float* bq = (const float*)d_in[2];
    const float* Wk = (const float*)d_in[3];
    const float* bk = (const float*)d_in[4];
    const float* Wv = (const float*)d_in[5];
    const float* bv = (const float*)d_in[6];
    float* out = (float*)d_out;

    __nv_bfloat16 *xhi, *xlo, *wvhi, *wvlo, *wqthi, *wqtlo, *wkthi, *wktlo;
    __nv_bfloat16 *mthi, *mtlo, *phi, *plo, *vthi, *vtlo, *ahi, *alo;
    float *sc, *tvec, *cst, *vrow, *zero;
    cudaGetSymbolAddress((void**)&xhi,   g_xhi);
    cudaGetSymbolAddress((void**)&xlo,   g_xlo);
    cudaGetSymbolAddress((void**)&wvhi,  g_wvhi);
    cudaGetSymbolAddress((void**)&wvlo,  g_wvlo);
    cudaGetSymbolAddress((void**)&wqthi, g_wqthi);
    cudaGetSymbolAddress((void**)&wqtlo, g_wqtlo);
    cudaGetSymbolAddress((void**)&wkthi, g_wkthi);
    cudaGetSymbolAddress((void**)&wktlo, g_wktlo);
    cudaGetSymbolAddress((void**)&mthi,  g_mthi);
    cudaGetSymbolAddress((void**)&mtlo,  g_mtlo);
    cudaGetSymbolAddress((void**)&phi,   g_phi);
    cudaGetSymbolAddress((void**)&plo,   g_plo);
    cudaGetSymbolAddress((void**)&vthi,  g_vthi);
    cudaGetSymbolAddress((void**)&vtlo,  g_vtlo);
    cudaGetSymbolAddress((void**)&sc,    g_s);
    cudaGetSymbolAddress((void**)&ahi,   g_ahi);
    cudaGetSymbolAddress((void**)&alo,   g_alo);
    cudaGetSymbolAddress((void**)&tvec,  g_tvec);
    cudaGetSymbolAddress((void**)&cst,   g_cst);
    cudaGetSymbolAddress((void**)&vrow,  g_vrow);
    cudaGetSymbolAddress((void**)&zero,  g_zero);

    cudaFuncSetAttribute(gemm_bf16x3<0>, cudaFuncAttributeMaxDynamicSharedMemorySize, SMEM_TOTAL);
    cudaFuncSetAttribute(gemm_bf16x3<1>, cudaFuncAttributeMaxDynamicSharedMemorySize, SMEM_TOTAL);
    cudaFuncSetAttribute(gemm_bf16x3<2>, cudaFuncAttributeMaxDynamicSharedMemorySize, SMEM_TOTAL);

    const long nxd = (long)NROWS * DIM;
    const long nww = (long)DIM * DIM;

    // pre-passes
    split_kernel<<<(int)(nxd / 4 / 256), 256>>>(x,  xhi,  xlo,  nxd);
    split_kernel<<<(int)(nww / 4 / 256), 256>>>(Wv, wvhi, wvlo, nww);
    {
        dim3 grid(DIM / 32, DIM / 32);
        dim3 blk(32, 8);
        transpose_split_kernel<<<grid, blk>>>(Wq, wqthi, wqtlo, DIM, DIM);
        transpose_split_kernel<<<grid, blk>>>(Wk, wkthi, wktlo, DIM, DIM);
    }
    t_kernel<<<DIM / 256, 256>>>(Wk, bq, bk, tvec, cst);
    v_kernel<<<NROWS / 8, 256>>>(x, tvec, cst, vrow);

    // Mt[d',d] = sum_e Wk[e,d'] Wq[e,d] -> split out
    {
        dim3 grid(DIM / 128, DIM / 128, 1);
        gemm_bf16x3<1><<<grid, 256, SMEM_TOTAL>>>(wkthi, wktlo, wqthi, wqtlo, zero,
                                                  nullptr, mthi, mtlo,
                                                  DIM, DIM, DIM, DIM, 0, 0, 0, 1.0f);
    }
    // P[s,d'] = sum_d x[s,d] Mt[d',d] -> split out
    {
        dim3 grid(NROWS / 128, DIM / 128, 1);
        gemm_bf16x3<1><<<grid, 256, SMEM_TOTAL>>>(xhi, xlo, mthi, mtlo, zero,
                                                  nullptr, phi, plo,
                                                  DIM, DIM, DIM, DIM, 0, 0, 0, 1.0f);
    }
    // Vt[d,s] = sum_k Wv[d,k] x[s,k] + bv[d] (row bias) -> split out, [D, B*S]
    {
        dim3 grid(DIM / 128, NROWS / 128, 1);
        gemm_bf16x3<2><<<grid, 256, SMEM_TOTAL>>>(wvhi, wvlo, xhi, xlo, bv,
                                                  nullptr, vthi, vtlo,
                                                  DIM, DIM, DIM, NROWS, 0, 0, 0, 1.0f);
    }
    // scores: per batch  P[2048,1024] x x[2048,1024]^T * 1/32 -> fp32
    {
        dim3 grid(SEQ / 128, SEQ / 128, BATCH);
        gemm_bf16x3<0><<<grid, 256, SMEM_TOTAL>>>(phi, plo, xhi, xlo, nullptr,
                                                  sc, nullptr, nullptr,
                                                  DIM, DIM, DIM, SEQ,
                                                  (long)SEQ * DIM, (long)SEQ * DIM,
                                                  (long)SEQ * SEQ, 1.0f / 32.0f);
    }
    // softmax(scores + v[col]) + split attn
    softmax_split_kernel<<<NROWS, 256>>>(sc, vrow, ahi, alo);

    // out: per batch attn[2048,2048] x Vt[:, b*2048 : (b+1)*2048]^T -> fp32
    {
        dim3 grid(SEQ / 128, DIM / 128, BATCH);
        gemm_bf16x3<0><<<grid, 256, SMEM_TOTAL>>>(ahi, alo, vthi, vtlo, nullptr,
                                                  out, nullptr, nullptr,
                                                  SEQ, SEQ, NROWS, DIM,
                                                  (long)SEQ * SEQ, (long)SEQ,
                                                  (long)SEQ * DIM, 1.0f);
    }
}